// round 1
// baseline (speedup 1.0000x reference)
#include <cuda_runtime.h>
#include <math.h>

#define T_TYPES 2
#define B_SZ 16
#define L_SZ 2048
#define N_EV 4096          // T*L
#define D_EMBD 512
#define G_SZ 1024
#define NPAIR 256          // D/2
#define TAB_HALF 16384
#define TAB_N 32768        // entries 0..TAB_N inclusive
#define TAB_SCALE 16.0f    // 1/h, h = 1/16
#define INV_SQRT_D 0.04419417382415922f

// ---------------- device scratch (statics: allowed; no cudaMalloc) ----------
__device__ double g_omega[NPAIR];                              // 10000^(-i/256)
__device__ float  g_table[TAB_N + 1];                          // f(delta) table
__device__ float  g_c[T_TYPES * G_SZ];                         // type_emb . q[g]
__device__ float  g_emb[(size_t)B_SZ * N_EV * D_EMBD];         // 134 MB
__device__ float  g_scores[(size_t)B_SZ * G_SZ * N_EV];        // 268 MB  [b][g][n]
__device__ float  g_mx[B_SZ * G_SZ];
__device__ float  g_inv[B_SZ * G_SZ];

__device__ __forceinline__ float reduce_angle(double phase) {
    const double TWO_PI  = 6.283185307179586476925286766559;
    const double INV_2PI = 0.15915494309189533576888376337251;
    double k = rint(phase * INV_2PI);
    return (float)fma(-k, TWO_PI, phase);   // |r| <= pi, exact enough
}

__global__ void k_omega() {
    int i = threadIdx.x;
    g_omega[i] = pow(10000.0, -(double)i / 256.0);
}

// f(delta) = sum_i cos(delta * omega_i), one block per table entry
__global__ void k_table() {
    __shared__ float red[256];
    int j = blockIdx.x;
    int i = threadIdx.x;
    double delta = -1024.0 + (double)j * (1.0 / 16.0);
    float r = reduce_angle(delta * g_omega[i]);
    red[i] = __cosf(r);
    __syncthreads();
    #pragma unroll
    for (int s = 128; s > 0; s >>= 1) {
        if (i < s) red[i] += red[i + s];
        __syncthreads();
    }
    if (i == 0) g_table[j] = red[0];
}

// c[t][g] = type_emb[t,:] . q[g,:]
__global__ void k_c(const float* __restrict__ type_emb) {
    __shared__ float red[256];
    int g = blockIdx.x, t = blockIdx.y, i = threadIdx.x;
    double m = (double)g + 0.5;
    float r = reduce_angle(m * g_omega[i]);
    float s, c;
    __sincosf(r, &s, &c);
    red[i] = type_emb[t * D_EMBD + 2 * i] * s + type_emb[t * D_EMBD + 2 * i + 1] * c;
    __syncthreads();
    #pragma unroll
    for (int st = 128; st > 0; st >>= 1) {
        if (i < st) red[i] += red[i + st];
        __syncthreads();
    }
    if (i == 0) g_c[t * G_SZ + g] = red[0];
}

// emb[b][n][d] = (sinusoid(t/p) + type_emb) * (t != 0)
__global__ void k_emb(const float* __restrict__ times, const float* __restrict__ type_emb) {
    int n = blockIdx.x, b = blockIdx.y, i = threadIdx.x;
    int tIdx = n >> 11, l = n & 2047;
    float tm = times[(size_t)tIdx * (B_SZ * L_SZ) + (size_t)b * L_SZ + l];
    float2 o;
    if (tm != 0.0f) {
        float r = reduce_angle((double)tm * g_omega[i]);
        float s, c;
        __sincosf(r, &s, &c);
        float2 te = *(const float2*)&type_emb[tIdx * D_EMBD + 2 * i];
        o.x = s + te.x;
        o.y = c + te.y;
    } else {
        o.x = 0.0f; o.y = 0.0f;
    }
    *(float2*)&g_emb[((size_t)b * N_EV + n) * D_EMBD + 2 * i] = o;
}

// scores[b][g][n] = (f(t_n - m_g) + c[type,g]) / sqrt(D)  (0 if t_n == 0)
// fused online softmax stats (max, inv-sum) over valid n per (b,g)
__global__ void k_scores(const float* __restrict__ times, const int* __restrict__ real_len) {
    extern __shared__ float sm[];
    float* tab = sm;                 // TAB_N+1 floats
    float* ts  = sm + (TAB_N + 1);   // N_EV floats
    int tid = threadIdx.x;
    int b = blockIdx.y;
    for (int j = tid; j <= TAB_N; j += 512) tab[j] = g_table[j];
    for (int j = tid; j < N_EV; j += 512) {
        int tIdx = j >> 11, l = j & 2047;
        ts[j] = times[(size_t)tIdx * (B_SZ * L_SZ) + (size_t)b * L_SZ + l];
    }
    __syncthreads();
    int rl0 = real_len[b], rl1 = real_len[B_SZ + b];
    int warp = tid >> 5, lane = tid & 31;
    const float NEG_INF = __int_as_float(0xff800000);

    #pragma unroll
    for (int gg = 0; gg < 2; gg++) {
        int g = blockIdx.x * 32 + gg * 16 + warp;
        float c0 = g_c[g], c1 = g_c[G_SZ + g];
        float mg = (float)g + 0.5f;
        float* row = g_scores + ((size_t)(b * G_SZ + g) << 12);
        float m_run = NEG_INF, s_run = 0.0f;
        for (int n = lane; n < N_EV; n += 32) {
            float tm = ts[n];
            float s = 0.0f;
            if (tm != 0.0f) {
                float x  = (tm - mg) * TAB_SCALE;
                float xf = floorf(x);
                int  idx = (int)xf + TAB_HALF;
                float fr = x - xf;
                float t0 = tab[idx], t1 = tab[idx + 1];
                float v  = fmaf(fr, t1 - t0, t0);
                s = (v + ((n < L_SZ) ? c0 : c1)) * INV_SQRT_D;
            }
            row[n] = s;
            int rl = (n < L_SZ) ? rl0 : rl1;
            if ((n & 2047) < rl) {
                if (s > m_run) {
                    s_run = s_run * __expf(m_run - s) + 1.0f;
                    m_run = s;
                } else {
                    s_run += __expf(s - m_run);
                }
            }
        }
        #pragma unroll
        for (int off = 16; off; off >>= 1) {
            float m2 = __shfl_xor_sync(0xffffffffu, m_run, off);
            float s2 = __shfl_xor_sync(0xffffffffu, s_run, off);
            float mn = fmaxf(m_run, m2);
            float a  = (m_run == mn) ? s_run : s_run * __expf(m_run - mn);
            float bb = (m2   == mn) ? s2    : s2    * __expf(m2   - mn);
            m_run = mn; s_run = a + bb;
        }
        if (lane == 0) {
            g_mx[b * G_SZ + g]  = m_run;
            g_inv[b * G_SZ + g] = 1.0f / s_run;
        }
    }
}

// out[b][g][d] = sum_n w[b][n][g] * emb[b][n][d] ; w = valid ? exp(s-m)*inv : 0
// 128(g) x 128(d) x 8(n) fp32 SGEMM, 256 threads, 8x8 per thread
__global__ void __launch_bounds__(256) k_gemm(const int* __restrict__ real_len,
                                              float* __restrict__ out) {
    __shared__ float As[8][128];
    __shared__ float Bs[8][128];
    int tid = threadIdx.x;
    int b  = blockIdx.z;
    int g0 = blockIdx.y * 128;
    int d0 = blockIdx.x * 128;
    int tx = tid & 15, ty = tid >> 4;
    int gA = tid >> 1;        // 0..127  (A-load row)
    int nh = tid & 1;         // which half of 8 n's
    float mgv = g_mx[b * G_SZ + g0 + gA];
    float ivv = g_inv[b * G_SZ + g0 + gA];
    int rl0 = real_len[b], rl1 = real_len[B_SZ + b];
    int rB = tid >> 5;        // 0..7  (B-load row)
    int dB = tid & 31;        // 0..31 (B-load float4 col)

    float acc[8][8];
    #pragma unroll
    for (int i = 0; i < 8; i++)
        #pragma unroll
        for (int j = 0; j < 8; j++) acc[i][j] = 0.0f;

    const float* srow = g_scores + ((size_t)(b * G_SZ + g0 + gA) << 12);
    const float* ebase = g_emb + (size_t)b * N_EV * D_EMBD + d0;

    for (int k0 = 0; k0 < N_EV; k0 += 8) {
        float4 sv = *(const float4*)(srow + k0 + nh * 4);
        #pragma unroll
        for (int q = 0; q < 4; q++) {
            int n = k0 + nh * 4 + q;
            float s = (q == 0) ? sv.x : (q == 1) ? sv.y : (q == 2) ? sv.z : sv.w;
            int rl = (n < L_SZ) ? rl0 : rl1;
            float w = ((n & 2047) < rl) ? __expf(s - mgv) * ivv : 0.0f;
            As[nh * 4 + q][gA] = w;
        }
        float4 ev = *(const float4*)(ebase + (size_t)(k0 + rB) * D_EMBD + dB * 4);
        *(float4*)&Bs[rB][dB * 4] = ev;
        __syncthreads();
        #pragma unroll
        for (int kk = 0; kk < 8; kk++) {
            float a[8], bb[8];
            *(float4*)(a)      = *(const float4*)&As[kk][ty * 8];
            *(float4*)(a + 4)  = *(const float4*)&As[kk][ty * 8 + 4];
            *(float4*)(bb)     = *(const float4*)&Bs[kk][tx * 8];
            *(float4*)(bb + 4) = *(const float4*)&Bs[kk][tx * 8 + 4];
            #pragma unroll
            for (int i = 0; i < 8; i++)
                #pragma unroll
                for (int j = 0; j < 8; j++)
                    acc[i][j] = fmaf(a[i], bb[j], acc[i][j]);
        }
        __syncthreads();
    }
    #pragma unroll
    for (int i = 0; i < 8; i++) {
        size_t o = ((size_t)(b * G_SZ + g0 + ty * 8 + i)) * D_EMBD + d0 + tx * 8;
        *(float4*)(out + o)     = *(float4*)&acc[i][0];
        *(float4*)(out + o + 4) = *(float4*)&acc[i][4];
    }
}

extern "C" void kernel_launch(void* const* d_in, const int* in_sizes, int n_in,
                              void* d_out, int out_size) {
    const float* times    = (const float*)d_in[0];
    const float* type_emb = (const float*)d_in[1];
    const int*   real_len = (const int*)d_in[2];
    float* out = (float*)d_out;
    (void)in_sizes; (void)n_in; (void)out_size;

    size_t smem_sc = (size_t)(TAB_N + 1 + N_EV) * sizeof(float);   // ~147.5 KB
    cudaFuncSetAttribute(k_scores, cudaFuncAttributeMaxDynamicSharedMemorySize,
                         (int)smem_sc);

    k_omega<<<1, NPAIR>>>();
    k_table<<<TAB_N + 1, 256>>>();
    k_c<<<dim3(G_SZ, T_TYPES), 256>>>(type_emb);
    k_emb<<<dim3(N_EV, B_SZ), NPAIR>>>(times, type_emb);
    k_scores<<<dim3(G_SZ / 32, B_SZ), 512, smem_sc>>>(times, real_len);
    k_gemm<<<dim3(D_EMBD / 128, G_SZ / 128, B_SZ), 256>>>(real_len, out);
}

// round 4
// speedup vs baseline: 3.6700x; 3.6700x over previous
#include <cuda_runtime.h>
#include <cuda_fp16.h>
#include <math.h>
#include <stdint.h>

#define T_TYPES 2
#define B_SZ 16
#define L_SZ 2048
#define N_EV 4096          // T*L
#define D_EMBD 512
#define G_SZ 1024
#define NPAIR 256          // D/2
#define TAB_N 16384        // symmetric table, u in [0,1024], h = 1/16
#define INV_SQRT_D 0.04419417382415922f

// ---------------- device scratch ----------------
__device__ double g_omega[NPAIR];
__device__ float2 g_tab[TAB_N + 1];                  // (H(u), H'(u)*h)
__device__ float  g_ec[T_TYPES * G_SZ];              // exp(type_emb . q[g] / sqrt(D))
__device__ float  g_sc[B_SZ * G_SZ];                 // max_raw / sum_raw
__device__ __align__(128) __half g_w[(size_t)B_SZ * G_SZ * N_EV];   // 128MB
__device__ __align__(128) __half g_e[(size_t)B_SZ * D_EMBD * N_EV]; // 64MB

// ---------------- helpers ----------------
__device__ __forceinline__ uint32_t smem_u32(const void* p) {
    uint32_t a;
    asm("{ .reg .u64 t; cvta.to.shared.u64 t, %1; cvt.u32.u64 %0, t; }" : "=r"(a) : "l"(p));
    return a;
}
__device__ __forceinline__ void cp16(uint32_t dst, const void* src) {
    asm volatile("cp.async.cg.shared.global [%0], [%1], 16;" :: "r"(dst), "l"(src));
}
__device__ __forceinline__ void ldm_x4(uint32_t (&r)[4], uint32_t addr) {
    asm volatile("ldmatrix.sync.aligned.m8n8.x4.shared.b16 {%0,%1,%2,%3}, [%4];"
                 : "=r"(r[0]), "=r"(r[1]), "=r"(r[2]), "=r"(r[3]) : "r"(addr));
}
__device__ __forceinline__ void mma16816(float (&c)[4], const uint32_t (&a)[4],
                                         uint32_t b0, uint32_t b1) {
    asm volatile("mma.sync.aligned.m16n8k16.row.col.f32.f16.f16.f32 "
                 "{%0,%1,%2,%3}, {%4,%5,%6,%7}, {%8,%9}, {%0,%1,%2,%3};"
                 : "+f"(c[0]), "+f"(c[1]), "+f"(c[2]), "+f"(c[3])
                 : "r"(a[0]), "r"(a[1]), "r"(a[2]), "r"(a[3]), "r"(b0), "r"(b1));
}
__device__ __forceinline__ float reduce_angle(double phase) {
    const double TWO_PI  = 6.283185307179586476925286766559;
    const double INV_2PI = 0.15915494309189533576888376337251;
    double k = rint(phase * INV_2PI);
    return (float)fma(-k, TWO_PI, phase);
}

// ---------------- setup kernels ----------------
__global__ void k_omega() {
    int i = threadIdx.x;
    g_omega[i] = pow(10000.0, -(double)i / 256.0);
}

// H(u) = exp(f(u)/sqrt(D)), f(u) = sum_i cos(u*w_i); H' = -H * sum(w sin)/sqrt(D)
__global__ void k_table() {
    __shared__ float rc[256], rs[256];
    int j = blockIdx.x, i = threadIdx.x;
    double u = (double)j * (1.0 / 16.0);
    double om = g_omega[i];
    float r = reduce_angle(u * om);
    float s, c; __sincosf(r, &s, &c);
    rc[i] = c;
    rs[i] = (float)om * s;
    __syncthreads();
    #pragma unroll
    for (int st = 128; st > 0; st >>= 1) {
        if (i < st) { rc[i] += rc[i + st]; rs[i] += rs[i + st]; }
        __syncthreads();
    }
    if (i == 0) {
        float H  = expf(rc[0] * INV_SQRT_D);
        float Hp = -H * rs[0] * INV_SQRT_D;
        g_tab[j] = make_float2(H, Hp * (1.0f / 16.0f));
    }
}

__global__ void k_ec(const float* __restrict__ type_emb) {
    __shared__ float red[256];
    int g = blockIdx.x, t = blockIdx.y, i = threadIdx.x;
    float r = reduce_angle(((double)g + 0.5) * g_omega[i]);
    float s, c; __sincosf(r, &s, &c);
    red[i] = type_emb[t * D_EMBD + 2 * i] * s + type_emb[t * D_EMBD + 2 * i + 1] * c;
    __syncthreads();
    #pragma unroll
    for (int st = 128; st > 0; st >>= 1) { if (i < st) red[i] += red[i + st]; __syncthreads(); }
    if (i == 0) g_ec[t * G_SZ + g] = expf(red[0] * INV_SQRT_D);
}

// emb transposed to [b][d][n] fp16
__global__ void k_emb_t(const float* __restrict__ times, const float* __restrict__ type_emb) {
    extern __shared__ float smE[];
    float* ebuf = smE;                 // 512*33
    float* tms  = smE + 512 * 33;      // 32
    int tid = threadIdx.x;             // 256
    int b = blockIdx.y;
    int n0 = blockIdx.x * 32;
    int tIdx = n0 >> 11;
    if (tid < 32) {
        int n = n0 + tid, l = n & 2047;
        tms[tid] = times[(size_t)tIdx * (B_SZ * L_SZ) + (size_t)b * L_SZ + l];
    }
    __syncthreads();
    int i = tid;
    float2 te = *(const float2*)&type_emb[tIdx * D_EMBD + 2 * i];
    double om = g_omega[i];
    #pragma unroll 4
    for (int j = 0; j < 32; j++) {
        float tm = tms[j];
        float ex = 0.f, ey = 0.f;
        if (tm != 0.f) {
            float r = reduce_angle((double)tm * om);
            float s, c; __sincosf(r, &s, &c);
            ex = s + te.x; ey = c + te.y;
        }
        ebuf[(2 * i) * 33 + j]     = ex;
        ebuf[(2 * i + 1) * 33 + j] = ey;
    }
    __syncthreads();
    uint32_t base = (uint32_t)b * (D_EMBD * N_EV) + n0;
    for (int idx = tid; idx < 512 * 8; idx += 256) {
        int d = idx >> 3, q = idx & 7;
        float v0 = ebuf[d * 33 + q * 4 + 0];
        float v1 = ebuf[d * 33 + q * 4 + 1];
        float v2 = ebuf[d * 33 + q * 4 + 2];
        float v3 = ebuf[d * 33 + q * 4 + 3];
        __half2 p0 = __floats2half2_rn(v0, v1);
        __half2 p1 = __floats2half2_rn(v2, v3);
        uint2 pk = make_uint2(*(uint32_t*)&p0, *(uint32_t*)&p1);
        *(uint2*)&g_e[base + (uint32_t)d * N_EV + q * 4] = pk;
    }
}

// unnormalized weight of event n for grid g (cubic Hermite on symmetric H table)
__device__ __forceinline__ float w_raw(const float2* tab, float tm, float mg, float ec) {
    float u  = fabsf(tm - mg);
    float x  = u * 16.f;
    float xf = floorf(x);
    int idx  = (int)xf;
    float fr = x - xf;
    float2 T0 = tab[idx];
    float2 T1 = tab[idx + 1];
    float t2 = fr * fr, t3 = t2 * fr;
    float p = T0.x * (2.f * t3 - 3.f * t2 + 1.f)
            + T0.y * (t3 - 2.f * t2 + fr)
            + T1.x * (3.f * t2 - 2.f * t3)
            + T1.y * (t3 - t2);
    return (tm != 0.f) ? p * ec : 1.0f;
}

// two-pass: (1) fp32 sum + max of raw weights; (2) store w_raw/max as fp16
__global__ void k_weights(const float* __restrict__ times, const int* __restrict__ real_len) {
    extern __shared__ float smW[];
    float2* tab = (float2*)smW;                     // TAB_N+1 float2
    float*  ts  = smW + 2 * (TAB_N + 1) + 2;        // +2 pad -> 16B aligned
    int tid = threadIdx.x;                          // 512
    int b = blockIdx.y;
    for (int j = tid; j <= TAB_N; j += 512) tab[j] = g_tab[j];
    for (int j = tid; j < N_EV; j += 512) {
        int tI = j >> 11, l = j & 2047;
        ts[j] = times[(size_t)tI * (B_SZ * L_SZ) + (size_t)b * L_SZ + l];
    }
    __syncthreads();
    int rl0 = real_len[b], rl1 = real_len[B_SZ + b];
    int warp = tid >> 5, lane = tid & 31;
    int g = blockIdx.x * 16 + warp;
    float ec0 = g_ec[g], ec1 = g_ec[G_SZ + g];
    float mg = (float)g + 0.5f;
    uint32_t base = ((uint32_t)(b * G_SZ + g)) << 12;

    // pass 1: fp32 sum + max of raw weights over valid events
    float sum = 0.f, mx = 0.f;
    #pragma unroll 2
    for (int it = 0; it < 32; it++) {
        int n0 = it * 128 + lane * 4;
        float4 t4 = *(const float4*)&ts[n0];
        int rl = (n0 < L_SZ) ? rl0 : rl1;
        float ec = (n0 < L_SZ) ? ec0 : ec1;
        #pragma unroll
        for (int q = 0; q < 4; q++) {
            float tm = (q == 0) ? t4.x : (q == 1) ? t4.y : (q == 2) ? t4.z : t4.w;
            float wr = w_raw(tab, tm, mg, ec);
            bool valid = ((n0 + q) & 2047) < rl;
            float w = valid ? wr : 0.f;
            sum += w;
            mx = fmaxf(mx, w);
        }
    }
    #pragma unroll
    for (int off = 16; off; off >>= 1) {
        sum += __shfl_xor_sync(0xffffffffu, sum, off);
        mx = fmaxf(mx, __shfl_xor_sync(0xffffffffu, mx, off));
    }
    float invmx = 1.0f / mx;
    if (lane == 0) g_sc[b * G_SZ + g] = mx / sum;

    // pass 2: store normalized-to-max weights as fp16
    #pragma unroll 2
    for (int it = 0; it < 32; it++) {
        int n0 = it * 128 + lane * 4;
        float4 t4 = *(const float4*)&ts[n0];
        int rl = (n0 < L_SZ) ? rl0 : rl1;
        float ec = (n0 < L_SZ) ? ec0 : ec1;
        float w[4];
        #pragma unroll
        for (int q = 0; q < 4; q++) {
            float tm = (q == 0) ? t4.x : (q == 1) ? t4.y : (q == 2) ? t4.z : t4.w;
            float wr = w_raw(tab, tm, mg, ec);
            bool valid = ((n0 + q) & 2047) < rl;
            w[q] = valid ? wr * invmx : 0.f;
        }
        __half2 p0 = __floats2half2_rn(w[0], w[1]);
        __half2 p1 = __floats2half2_rn(w[2], w[3]);
        uint2 pk = make_uint2(*(uint32_t*)&p0, *(uint32_t*)&p1);
        *(uint2*)&g_w[base + n0] = pk;
    }
}

// ---------------- fp16 mma.sync GEMM: out[b][g][d] = sc[g] * sum_n w*e ----------------
#define KTILE 32
#define STAGES 4
#define ROWB 80                        // padded row stride (bytes) for 64B of data
#define A_TILE_B (128 * ROWB)          // 10240
#define B_TILE_B (256 * ROWB)          // 20480
#define STG_B (A_TILE_B + B_TILE_B)    // 30720

__global__ void __launch_bounds__(256, 1) k_gemm(float* __restrict__ out) {
    extern __shared__ char smG[];
    uint32_t smb = smem_u32(smG);
    float* smInv = (float*)(smG + STAGES * STG_B);
    int tid = threadIdx.x, wid = tid >> 5, lane = tid & 31;
    int b  = blockIdx.z;
    int g0 = blockIdx.x * 128;
    int d0 = blockIdx.y * 256;
    int wm = wid >> 2, wn = wid & 3;

    if (tid < 128) smInv[tid] = g_sc[b * G_SZ + g0 + tid];

    const __half* wbase = g_w + (((uint32_t)(b * G_SZ + g0)) << 12);
    const __half* ebase = g_e + (((uint32_t)(b * D_EMBD + d0)) << 12);

    auto load_stage = [&](int s, int k0) {
        uint32_t st = smb + s * STG_B;
        #pragma unroll
        for (int t = 0; t < 2; t++) {
            int id = tid + t * 256;           // 512 A chunks
            int row = id >> 2, c = id & 3;
            cp16(st + row * ROWB + c * 16, wbase + ((uint32_t)row << 12) + k0 + c * 8);
        }
        #pragma unroll
        for (int t = 0; t < 4; t++) {
            int id = tid + t * 256;           // 1024 B chunks
            int row = id >> 2, c = id & 3;
            cp16(st + A_TILE_B + row * ROWB + c * 16,
                 ebase + ((uint32_t)row << 12) + k0 + c * 8);
        }
        asm volatile("cp.async.commit_group;" ::: "memory");
    };

    float acc[4][8][4];
    #pragma unroll
    for (int i = 0; i < 4; i++)
        #pragma unroll
        for (int j = 0; j < 8; j++)
            #pragma unroll
            for (int q = 0; q < 4; q++) acc[i][j][q] = 0.f;

    load_stage(0, 0);
    load_stage(1, KTILE);
    load_stage(2, 2 * KTILE);

    int a_row = (lane & 7) + ((lane >> 3) & 1) * 8;
    int a_col = (lane >> 4) * 16;
    int b_grp = lane >> 3;
    int b_row = (b_grp >> 1) * 8 + (lane & 7);
    int b_col = (b_grp & 1) * 16;

    for (int i = 0; i < 128; i++) {
        if (i <= 125)      asm volatile("cp.async.wait_group 2;" ::: "memory");
        else if (i == 126) asm volatile("cp.async.wait_group 1;" ::: "memory");
        else               asm volatile("cp.async.wait_group 0;" ::: "memory");
        __syncthreads();

        uint32_t abase = smb + (i & 3) * STG_B;
        uint32_t bbase = abase + A_TILE_B;
        #pragma unroll
        for (int ks = 0; ks < 2; ks++) {
            uint32_t af[4][4], bf[4][4];
            #pragma unroll
            for (int m = 0; m < 4; m++)
                ldm_x4(af[m], abase + (wm * 64 + m * 16 + a_row) * ROWB + ks * 32 + a_col);
            #pragma unroll
            for (int jp = 0; jp < 4; jp++)
                ldm_x4(bf[jp], bbase + (wn * 64 + jp * 16 + b_row) * ROWB + ks * 32 + b_col);
            #pragma unroll
            for (int m = 0; m < 4; m++)
                #pragma unroll
                for (int j = 0; j < 8; j++)
                    mma16816(acc[m][j], af[m], bf[j >> 1][(j & 1) * 2], bf[j >> 1][(j & 1) * 2 + 1]);
        }
        if (i < 125) load_stage((i + 3) & 3, (i + 3) * KTILE);
    }

    #pragma unroll
    for (int m = 0; m < 4; m++) {
        int r0 = wm * 64 + m * 16 + (lane >> 2);
        float sc0 = smInv[r0], sc1 = smInv[r0 + 8];
        uint32_t gr0 = (uint32_t)(b * G_SZ + g0 + r0) * D_EMBD;
        #pragma unroll
        for (int j = 0; j < 8; j++) {
            int col = d0 + wn * 64 + j * 8 + (lane & 3) * 2;
            *(float2*)(out + gr0 + col) =
                make_float2(acc[m][j][0] * sc0, acc[m][j][1] * sc0);
            *(float2*)(out + gr0 + 8 * D_EMBD + col) =
                make_float2(acc[m][j][2] * sc1, acc[m][j][3] * sc1);
        }
    }
}

// ---------------- launch ----------------
extern "C" void kernel_launch(void* const* d_in, const int* in_sizes, int n_in,
                              void* d_out, int out_size) {
    const float* times    = (const float*)d_in[0];
    const float* type_emb = (const float*)d_in[1];
    const int*   real_len = (const int*)d_in[2];
    float* out = (float*)d_out;
    (void)in_sizes; (void)n_in; (void)out_size;

    size_t smem_e = (size_t)(512 * 33 + 32) * sizeof(float);                 // ~67.7 KB
    size_t smem_w = (size_t)(2 * (TAB_N + 1) + 2 + N_EV) * sizeof(float);    // ~147.5 KB
    size_t smem_g = STAGES * STG_B + 128 * sizeof(float);                    // ~123.4 KB
    cudaFuncSetAttribute(k_emb_t,   cudaFuncAttributeMaxDynamicSharedMemorySize, (int)smem_e);
    cudaFuncSetAttribute(k_weights, cudaFuncAttributeMaxDynamicSharedMemorySize, (int)smem_w);
    cudaFuncSetAttribute(k_gemm,    cudaFuncAttributeMaxDynamicSharedMemorySize, (int)smem_g);

    k_omega<<<1, NPAIR>>>();
    k_table<<<TAB_N + 1, 256>>>();
    k_ec<<<dim3(G_SZ, T_TYPES), 256>>>(type_emb);
    k_emb_t<<<dim3(N_EV / 32, B_SZ), 256, smem_e>>>(times, type_emb);
    k_weights<<<dim3(G_SZ / 16, B_SZ), 512, smem_w>>>(times, real_len);
    k_gemm<<<dim3(G_SZ / 128, D_EMBD / 256, B_SZ), 256, smem_g>>>(out);
}

// round 5
// speedup vs baseline: 5.0095x; 1.3650x over previous
#include <cuda_runtime.h>
#include <cuda_fp16.h>
#include <math.h>
#include <stdint.h>

#define T_TYPES 2
#define B_SZ 16
#define L_SZ 2048
#define N_EV 4096          // T*L
#define D_EMBD 512
#define G_SZ 1024
#define NPAIR 256          // D/2
#define TAB_N 8192         // symmetric table, u in [0,1024], h = 1/8
#define INV_SQRT_D 0.04419417382415922f

// ---------------- device scratch ----------------
__device__ double g_omega[NPAIR];
__device__ float  g_omf[NPAIR];
__device__ float2 g_tab[TAB_N + 1];                  // (H(u), H'(u)*h)
__device__ float  g_ec[T_TYPES * G_SZ];              // exp(type_emb . q[g] / sqrt(D))
__device__ float  g_sc[B_SZ * G_SZ];                 // max_raw / sum_raw
__device__ __align__(128) __half g_w[(size_t)B_SZ * G_SZ * N_EV];   // 128MB
__device__ __align__(128) __half g_e[(size_t)B_SZ * D_EMBD * N_EV]; // 64MB

// ---------------- helpers ----------------
__device__ __forceinline__ uint32_t smem_u32(const void* p) {
    uint32_t a;
    asm("{ .reg .u64 t; cvta.to.shared.u64 t, %1; cvt.u32.u64 %0, t; }" : "=r"(a) : "l"(p));
    return a;
}
__device__ __forceinline__ void cp16(uint32_t dst, const void* src) {
    asm volatile("cp.async.cg.shared.global [%0], [%1], 16;" :: "r"(dst), "l"(src));
}
__device__ __forceinline__ void ldm_x4(uint32_t (&r)[4], uint32_t addr) {
    asm volatile("ldmatrix.sync.aligned.m8n8.x4.shared.b16 {%0,%1,%2,%3}, [%4];"
                 : "=r"(r[0]), "=r"(r[1]), "=r"(r[2]), "=r"(r[3]) : "r"(addr));
}
__device__ __forceinline__ void mma16816(float (&c)[4], const uint32_t (&a)[4],
                                         uint32_t b0, uint32_t b1) {
    asm volatile("mma.sync.aligned.m16n8k16.row.col.f32.f16.f16.f32 "
                 "{%0,%1,%2,%3}, {%4,%5,%6,%7}, {%8,%9}, {%0,%1,%2,%3};"
                 : "+f"(c[0]), "+f"(c[1]), "+f"(c[2]), "+f"(c[3])
                 : "r"(a[0]), "r"(a[1]), "r"(a[2]), "r"(a[3]), "r"(b0), "r"(b1));
}
__device__ __forceinline__ float reduce_angle(double phase) {
    const double TWO_PI  = 6.283185307179586476925286766559;
    const double INV_2PI = 0.15915494309189533576888376337251;
    double k = rint(phase * INV_2PI);
    return (float)fma(-k, TWO_PI, phase);
}
// fp32 Cody-Waite range reduction: x in [0, 1024], returns r ~ x mod 2pi, |r| <= pi
__device__ __forceinline__ float reduce_f32(float x) {
    const float INV2PI = 0.15915494309189535f;
    const float C1 = 6.28125f;                  // 7-bit mantissa: k*C1 exact for k<2^17
    const float C2 = 1.9353071795864769e-3f;
    float kf = rintf(x * INV2PI);
    float r = fmaf(-kf, C1, x);
    return fmaf(-kf, C2, r);
}

// ---------------- setup kernels ----------------
__global__ void k_omega() {
    int i = threadIdx.x;
    double om = pow(10000.0, -(double)i / 256.0);
    g_omega[i] = om;
    g_omf[i] = (float)om;
}

// H(u) = exp(f(u)/sqrt(D)), f(u) = sum_i cos(u*w_i); H' = -H * sum(w sin)/sqrt(D)
__global__ void k_table() {
    __shared__ float rc[256], rs[256];
    int j = blockIdx.x, i = threadIdx.x;
    double u = (double)j * 0.125;
    double om = g_omega[i];
    float r = reduce_angle(u * om);
    float s, c; __sincosf(r, &s, &c);
    rc[i] = c;
    rs[i] = (float)om * s;
    __syncthreads();
    #pragma unroll
    for (int st = 128; st > 0; st >>= 1) {
        if (i < st) { rc[i] += rc[i + st]; rs[i] += rs[i + st]; }
        __syncthreads();
    }
    if (i == 0) {
        float H  = expf(rc[0] * INV_SQRT_D);
        float Hp = -H * rs[0] * INV_SQRT_D;
        g_tab[j] = make_float2(H, Hp * 0.125f);
    }
}

__global__ void k_ec(const float* __restrict__ type_emb) {
    __shared__ float red[256];
    int g = blockIdx.x, t = blockIdx.y, i = threadIdx.x;
    float r = reduce_angle(((double)g + 0.5) * g_omega[i]);
    float s, c; __sincosf(r, &s, &c);
    red[i] = type_emb[t * D_EMBD + 2 * i] * s + type_emb[t * D_EMBD + 2 * i + 1] * c;
    __syncthreads();
    #pragma unroll
    for (int st = 128; st > 0; st >>= 1) { if (i < st) red[i] += red[i + st]; __syncthreads(); }
    if (i == 0) g_ec[t * G_SZ + g] = expf(red[0] * INV_SQRT_D);
}

// emb to [b][d][n] fp16 — no smem, no fp64; warp = 32 consecutive n, loop over i
__global__ void __launch_bounds__(256) k_emb_t(const float* __restrict__ times,
                                               const float* __restrict__ type_emb) {
    int lane = threadIdx.x & 31, w = threadIdx.x >> 5;   // 8 warps
    int b = blockIdx.y;
    int n0 = blockIdx.x * 32;
    int tIdx = n0 >> 11;
    int l = (n0 + lane) & 2047;
    float tm = times[(size_t)tIdx * (B_SZ * L_SZ) + (size_t)b * L_SZ + l];
    bool nz = (tm != 0.f);
    uint32_t base = (uint32_t)b * (D_EMBD * N_EV) + n0 + lane;
    #pragma unroll 4
    for (int ii = 0; ii < 32; ii++) {
        int i = w + ii * 8;                              // pair index 0..255
        float x = tm * g_omf[i];
        float r = reduce_f32(x);
        float s, c; __sincosf(r, &s, &c);
        float2 te = *(const float2*)&type_emb[tIdx * D_EMBD + 2 * i];
        __half h0 = __float2half_rn(nz ? s + te.x : 0.f);
        __half h1 = __float2half_rn(nz ? c + te.y : 0.f);
        g_e[base + (uint32_t)(2 * i) * N_EV]     = h0;
        g_e[base + (uint32_t)(2 * i + 1) * N_EV] = h1;
    }
}

// unnormalized weight (cubic Hermite, Horner form, symmetric H table, h=1/8)
__device__ __forceinline__ float w_raw(const float2* tab, float tm, float mg, float ec) {
    float u  = fabsf(tm - mg);
    float x  = u * 8.f;
    float xf = floorf(x);
    int idx  = (int)xf;
    float fr = x - xf;
    float2 T0 = tab[idx];
    float2 T1 = tab[idx + 1];
    float d  = T1.x - T0.x;
    float qa = 3.f * d - 2.f * T0.y - T1.y;
    float qb = T0.y + T1.y - 2.f * d;
    float p  = fmaf(fr, fmaf(fr, fmaf(fr, qb, qa), T0.y), T0.x);
    return (tm != 0.f) ? p * ec : 1.0f;
}

// two-pass: (1) fp32 sum + max of raw weights; (2) store w_raw/max as fp16
__global__ void __launch_bounds__(512) k_weights(const float* __restrict__ times,
                                                 const int* __restrict__ real_len) {
    extern __shared__ float smW[];
    float2* tab = (float2*)smW;                     // TAB_N+1 float2
    float*  ts  = smW + 2 * (TAB_N + 1) + 2;        // 16B aligned
    int tid = threadIdx.x;                          // 512
    int b = blockIdx.y;
    for (int j = tid; j <= TAB_N; j += 512) tab[j] = g_tab[j];
    for (int j = tid; j < N_EV; j += 512) {
        int tI = j >> 11, l = j & 2047;
        ts[j] = times[(size_t)tI * (B_SZ * L_SZ) + (size_t)b * L_SZ + l];
    }
    __syncthreads();
    int rl0 = real_len[b], rl1 = real_len[B_SZ + b];
    int warp = tid >> 5, lane = tid & 31;
    int g = blockIdx.x * 16 + warp;
    float ec0 = g_ec[g], ec1 = g_ec[G_SZ + g];
    float mg = (float)g + 0.5f;
    uint32_t base = ((uint32_t)(b * G_SZ + g)) << 12;

    float sum = 0.f, mx = 0.f;
    #pragma unroll 2
    for (int it = 0; it < 32; it++) {
        int n0 = it * 128 + lane * 4;
        float4 t4 = *(const float4*)&ts[n0];
        int rl = (n0 < L_SZ) ? rl0 : rl1;
        float ec = (n0 < L_SZ) ? ec0 : ec1;
        #pragma unroll
        for (int q = 0; q < 4; q++) {
            float tm = (q == 0) ? t4.x : (q == 1) ? t4.y : (q == 2) ? t4.z : t4.w;
            float wr = w_raw(tab, tm, mg, ec);
            bool valid = ((n0 + q) & 2047) < rl;
            float w = valid ? wr : 0.f;
            sum += w;
            mx = fmaxf(mx, w);
        }
    }
    #pragma unroll
    for (int off = 16; off; off >>= 1) {
        sum += __shfl_xor_sync(0xffffffffu, sum, off);
        mx = fmaxf(mx, __shfl_xor_sync(0xffffffffu, mx, off));
    }
    float invmx = 1.0f / mx;
    if (lane == 0) g_sc[b * G_SZ + g] = mx / sum;

    #pragma unroll 2
    for (int it = 0; it < 32; it++) {
        int n0 = it * 128 + lane * 4;
        float4 t4 = *(const float4*)&ts[n0];
        int rl = (n0 < L_SZ) ? rl0 : rl1;
        float ec = (n0 < L_SZ) ? ec0 : ec1;
        float w[4];
        #pragma unroll
        for (int q = 0; q < 4; q++) {
            float tm = (q == 0) ? t4.x : (q == 1) ? t4.y : (q == 2) ? t4.z : t4.w;
            float wr = w_raw(tab, tm, mg, ec);
            bool valid = ((n0 + q) & 2047) < rl;
            w[q] = valid ? wr * invmx : 0.f;
        }
        __half2 p0 = __floats2half2_rn(w[0], w[1]);
        __half2 p1 = __floats2half2_rn(w[2], w[3]);
        uint2 pk = make_uint2(*(uint32_t*)&p0, *(uint32_t*)&p1);
        *(uint2*)&g_w[base + n0] = pk;
    }
}

// ---------------- fp16 mma.sync GEMM: out[b][g][d] = sc[g] * sum_n w*e ----------------
#define KTILE 32
#define STAGES 4
#define ROWB 80                        // padded row stride (bytes) for 64B of data
#define A_TILE_B (128 * ROWB)          // 10240
#define B_TILE_B (256 * ROWB)          // 20480
#define STG_B (A_TILE_B + B_TILE_B)    // 30720

__global__ void __launch_bounds__(256, 1) k_gemm(float* __restrict__ out) {
    extern __shared__ char smG[];
    uint32_t smb = smem_u32(smG);
    float* smInv = (float*)(smG + STAGES * STG_B);
    int tid = threadIdx.x, wid = tid >> 5, lane = tid & 31;
    int b  = blockIdx.z;
    int g0 = blockIdx.x * 128;
    int d0 = blockIdx.y * 256;
    int wm = wid >> 2, wn = wid & 3;

    if (tid < 128) smInv[tid] = g_sc[b * G_SZ + g0 + tid];

    const __half* wbase = g_w + (((uint32_t)(b * G_SZ + g0)) << 12);
    const __half* ebase = g_e + (((uint32_t)(b * D_EMBD + d0)) << 12);

    auto load_stage = [&](int s, int k0) {
        uint32_t st = smb + s * STG_B;
        #pragma unroll
        for (int t = 0; t < 2; t++) {
            int id = tid + t * 256;
            int row = id >> 2, c = id & 3;
            cp16(st + row * ROWB + c * 16, wbase + ((uint32_t)row << 12) + k0 + c * 8);
        }
        #pragma unroll
        for (int t = 0; t < 4; t++) {
            int id = tid + t * 256;
            int row = id >> 2, c = id & 3;
            cp16(st + A_TILE_B + row * ROWB + c * 16,
                 ebase + ((uint32_t)row << 12) + k0 + c * 8);
        }
        asm volatile("cp.async.commit_group;" ::: "memory");
    };

    float acc[4][8][4];
    #pragma unroll
    for (int i = 0; i < 4; i++)
        #pragma unroll
        for (int j = 0; j < 8; j++)
            #pragma unroll
            for (int q = 0; q < 4; q++) acc[i][j][q] = 0.f;

    load_stage(0, 0);
    load_stage(1, KTILE);
    load_stage(2, 2 * KTILE);

    int a_row = (lane & 7) + ((lane >> 3) & 1) * 8;
    int a_col = (lane >> 4) * 16;
    int b_grp = lane >> 3;
    int b_row = (b_grp >> 1) * 8 + (lane & 7);
    int b_col = (b_grp & 1) * 16;

    for (int i = 0; i < 128; i++) {
        if (i <= 125)      asm volatile("cp.async.wait_group 2;" ::: "memory");
        else if (i == 126) asm volatile("cp.async.wait_group 1;" ::: "memory");
        else               asm volatile("cp.async.wait_group 0;" ::: "memory");
        __syncthreads();

        uint32_t abase = smb + (i & 3) * STG_B;
        uint32_t bbase = abase + A_TILE_B;
        #pragma unroll
        for (int ks = 0; ks < 2; ks++) {
            uint32_t af[4][4], bf[4][4];
            #pragma unroll
            for (int m = 0; m < 4; m++)
                ldm_x4(af[m], abase + (wm * 64 + m * 16 + a_row) * ROWB + ks * 32 + a_col);
            #pragma unroll
            for (int jp = 0; jp < 4; jp++)
                ldm_x4(bf[jp], bbase + (wn * 64 + jp * 16 + b_row) * ROWB + ks * 32 + b_col);
            #pragma unroll
            for (int m = 0; m < 4; m++)
                #pragma unroll
                for (int j = 0; j < 8; j++)
                    mma16816(acc[m][j], af[m], bf[j >> 1][(j & 1) * 2], bf[j >> 1][(j & 1) * 2 + 1]);
        }
        if (i < 125) load_stage((i + 3) & 3, (i + 3) * KTILE);
    }

    #pragma unroll
    for (int m = 0; m < 4; m++) {
        int r0 = wm * 64 + m * 16 + (lane >> 2);
        float sc0 = smInv[r0], sc1 = smInv[r0 + 8];
        uint32_t gr0 = (uint32_t)(b * G_SZ + g0 + r0) * D_EMBD;
        #pragma unroll
        for (int j = 0; j < 8; j++) {
            int col = d0 + wn * 64 + j * 8 + (lane & 3) * 2;
            *(float2*)(out + gr0 + col) =
                make_float2(acc[m][j][0] * sc0, acc[m][j][1] * sc0);
            *(float2*)(out + gr0 + 8 * D_EMBD + col) =
                make_float2(acc[m][j][2] * sc1, acc[m][j][3] * sc1);
        }
    }
}

// ---------------- launch ----------------
extern "C" void kernel_launch(void* const* d_in, const int* in_sizes, int n_in,
                              void* d_out, int out_size) {
    const float* times    = (const float*)d_in[0];
    const float* type_emb = (const float*)d_in[1];
    const int*   real_len = (const int*)d_in[2];
    float* out = (float*)d_out;
    (void)in_sizes; (void)n_in; (void)out_size;

    size_t smem_w = (size_t)(2 * (TAB_N + 1) + 2 + N_EV) * sizeof(float);    // ~80 KB
    size_t smem_g = STAGES * STG_B + 128 * sizeof(float);                    // ~123.4 KB
    cudaFuncSetAttribute(k_weights, cudaFuncAttributeMaxDynamicSharedMemorySize, (int)smem_w);
    cudaFuncSetAttribute(k_gemm,    cudaFuncAttributeMaxDynamicSharedMemorySize, (int)smem_g);

    k_omega<<<1, NPAIR>>>();
    k_table<<<TAB_N + 1, 256>>>();
    k_ec<<<dim3(G_SZ, T_TYPES), 256>>>(type_emb);
    k_emb_t<<<dim3(N_EV / 32, B_SZ), 256>>>(times, type_emb);
    k_weights<<<dim3(G_SZ / 16, B_SZ), 512, smem_w>>>(times, real_len);
    k_gemm<<<dim3(G_SZ / 128, D_EMBD / 256, B_SZ), 256, smem_g>>>(out);
}

// round 6
// speedup vs baseline: 6.4645x; 1.2904x over previous
#include <cuda_runtime.h>
#include <cuda_fp16.h>
#include <math.h>
#include <stdint.h>

#define T_TYPES 2
#define B_SZ 16
#define L_SZ 2048
#define N_EV 4096          // T*L
#define D_EMBD 512
#define G_SZ 1024
#define NPAIR 256          // D/2
#define TAB_N 8192         // symmetric table, u in [0,1024], h = 1/8
#define INV_SQRT_D 0.04419417382415922f

// ---------------- device scratch ----------------
__device__ double g_omega[NPAIR];
__device__ float  g_omf[NPAIR];
__device__ float2 g_tab[TAB_N + 1];                  // (H(u), H'(u)*h)
__device__ float  g_ec[T_TYPES * G_SZ];              // exp(type_emb . q[g] / sqrt(D))
__device__ float  g_sc[B_SZ * G_SZ];                 // 1 / sum(stored w)
__device__ __align__(128) __half g_w[(size_t)B_SZ * G_SZ * N_EV];   // 128MB
__device__ __align__(128) __half g_e[(size_t)B_SZ * D_EMBD * N_EV]; // 64MB

// ---------------- helpers ----------------
__device__ __forceinline__ uint32_t smem_u32(const void* p) {
    uint32_t a;
    asm("{ .reg .u64 t; cvta.to.shared.u64 t, %1; cvt.u32.u64 %0, t; }" : "=r"(a) : "l"(p));
    return a;
}
__device__ __forceinline__ void cp16(uint32_t dst, const void* src) {
    asm volatile("cp.async.cg.shared.global [%0], [%1], 16;" :: "r"(dst), "l"(src));
}
__device__ __forceinline__ void ldm_x4(uint32_t (&r)[4], uint32_t addr) {
    asm volatile("ldmatrix.sync.aligned.m8n8.x4.shared.b16 {%0,%1,%2,%3}, [%4];"
                 : "=r"(r[0]), "=r"(r[1]), "=r"(r[2]), "=r"(r[3]) : "r"(addr));
}
__device__ __forceinline__ void mma16816(float (&c)[4], const uint32_t (&a)[4],
                                         uint32_t b0, uint32_t b1) {
    asm volatile("mma.sync.aligned.m16n8k16.row.col.f32.f16.f16.f32 "
                 "{%0,%1,%2,%3}, {%4,%5,%6,%7}, {%8,%9}, {%0,%1,%2,%3};"
                 : "+f"(c[0]), "+f"(c[1]), "+f"(c[2]), "+f"(c[3])
                 : "r"(a[0]), "r"(a[1]), "r"(a[2]), "r"(a[3]), "r"(b0), "r"(b1));
}
__device__ __forceinline__ float reduce_angle(double phase) {
    const double TWO_PI  = 6.283185307179586476925286766559;
    const double INV_2PI = 0.15915494309189533576888376337251;
    double k = rint(phase * INV_2PI);
    return (float)fma(-k, TWO_PI, phase);
}
// fp32 Cody-Waite range reduction: x in [0, 1024], |r| <= pi
__device__ __forceinline__ float reduce_f32(float x) {
    const float INV2PI = 0.15915494309189535f;
    const float C1 = 6.28125f;
    const float C2 = 1.9353071795864769e-3f;
    float kf = rintf(x * INV2PI);
    float r = fmaf(-kf, C1, x);
    return fmaf(-kf, C2, r);
}

// ---------------- setup kernels ----------------
__global__ void k_omega() {
    int i = threadIdx.x;
    double om = pow(10000.0, -(double)i / 256.0);
    g_omega[i] = om;
    g_omf[i] = (float)om;
}

__global__ void k_table() {
    __shared__ float rc[256], rs[256];
    int j = blockIdx.x, i = threadIdx.x;
    double u = (double)j * 0.125;
    double om = g_omega[i];
    float r = reduce_angle(u * om);
    float s, c; __sincosf(r, &s, &c);
    rc[i] = c;
    rs[i] = (float)om * s;
    __syncthreads();
    #pragma unroll
    for (int st = 128; st > 0; st >>= 1) {
        if (i < st) { rc[i] += rc[i + st]; rs[i] += rs[i + st]; }
        __syncthreads();
    }
    if (i == 0) {
        float H  = expf(rc[0] * INV_SQRT_D);
        float Hp = -H * rs[0] * INV_SQRT_D;
        g_tab[j] = make_float2(H, Hp * 0.125f);
    }
}

__global__ void k_ec(const float* __restrict__ type_emb) {
    __shared__ float red[256];
    int g = blockIdx.x, t = blockIdx.y, i = threadIdx.x;
    float r = reduce_angle(((double)g + 0.5) * g_omega[i]);
    float s, c; __sincosf(r, &s, &c);
    red[i] = type_emb[t * D_EMBD + 2 * i] * s + type_emb[t * D_EMBD + 2 * i + 1] * c;
    __syncthreads();
    #pragma unroll
    for (int st = 128; st > 0; st >>= 1) { if (i < st) red[i] += red[i + st]; __syncthreads(); }
    if (i == 0) g_ec[t * G_SZ + g] = expf(red[0] * INV_SQRT_D);
}

// emb to [b][d][n] fp16 — no smem, no fp64
__global__ void __launch_bounds__(256) k_emb_t(const float* __restrict__ times,
                                               const float* __restrict__ type_emb) {
    int lane = threadIdx.x & 31, w = threadIdx.x >> 5;
    int b = blockIdx.y;
    int n0 = blockIdx.x * 32;
    int tIdx = n0 >> 11;
    int l = (n0 + lane) & 2047;
    float tm = times[(size_t)tIdx * (B_SZ * L_SZ) + (size_t)b * L_SZ + l];
    bool nz = (tm != 0.f);
    uint32_t base = (uint32_t)b * (D_EMBD * N_EV) + n0 + lane;
    #pragma unroll 4
    for (int ii = 0; ii < 32; ii++) {
        int i = w + ii * 8;
        float x = tm * g_omf[i];
        float r = reduce_f32(x);
        float s, c; __sincosf(r, &s, &c);
        float2 te = *(const float2*)&type_emb[tIdx * D_EMBD + 2 * i];
        __half h0 = __float2half_rn(nz ? s + te.x : 0.f);
        __half h1 = __float2half_rn(nz ? c + te.y : 0.f);
        g_e[base + (uint32_t)(2 * i) * N_EV]     = h0;
        g_e[base + (uint32_t)(2 * i + 1) * N_EV] = h1;
    }
}

// unnormalized weight (cubic Hermite, Horner form, symmetric H table, h=1/8)
__device__ __forceinline__ float w_raw(const float2* tab, float tm, float mg, float ec) {
    float u  = fabsf(tm - mg);
    float x  = u * 8.f;
    float xf = floorf(x);
    int idx  = (int)xf;
    float fr = x - xf;
    float2 T0 = tab[idx];
    float2 T1 = tab[idx + 1];
    float d  = T1.x - T0.x;
    float qa = 3.f * d - 2.f * T0.y - T1.y;
    float qb = T0.y + T1.y - 2.f * d;
    float p  = fmaf(fr, fmaf(fr, fmaf(fr, qb, qa), T0.y), T0.x);
    return (tm != 0.f) ? p * ec : 1.0f;
}

// single interp pass: bound from min-distance pre-pass (no LDS), then store
// w_raw/bound as fp16 and accumulate fp32 sum of the QUANTIZED values.
__global__ void __launch_bounds__(512) k_weights(const float* __restrict__ times,
                                                 const int* __restrict__ real_len) {
    extern __shared__ float smW[];
    float2* tab = (float2*)smW;                     // TAB_N+1 float2
    float*  ts  = smW + 2 * (TAB_N + 1) + 2;        // 16B aligned
    int tid = threadIdx.x;                          // 512
    int b = blockIdx.y;
    for (int j = tid; j <= TAB_N; j += 512) tab[j] = g_tab[j];
    for (int j = tid; j < N_EV; j += 512) {
        int tI = j >> 11, l = j & 2047;
        ts[j] = times[(size_t)tI * (B_SZ * L_SZ) + (size_t)b * L_SZ + l];
    }
    __syncthreads();
    int rl0 = real_len[b], rl1 = real_len[B_SZ + b];
    int warp = tid >> 5, lane = tid & 31;
    int g = blockIdx.x * 16 + warp;
    float ec0 = g_ec[g], ec1 = g_ec[G_SZ + g];
    float mg = (float)g + 0.5f;
    uint32_t base = ((uint32_t)(b * G_SZ + g)) << 12;

    // pass A (cheap): per-segment min distance among valid nonzero-time events
    float umin0 = 1e9f, umin1 = 1e9f;
    #pragma unroll 2
    for (int it = 0; it < 32; it++) {
        int n0 = it * 128 + lane * 4;
        float4 t4 = *(const float4*)&ts[n0];
        int rl = (n0 < L_SZ) ? rl0 : rl1;
        bool seg0 = (n0 < L_SZ);
        #pragma unroll
        for (int q = 0; q < 4; q++) {
            float tm = (q == 0) ? t4.x : (q == 1) ? t4.y : (q == 2) ? t4.z : t4.w;
            bool valid = (((n0 + q) & 2047) < rl) && (tm != 0.f);
            float u = valid ? fabsf(tm - mg) : 1e9f;
            if (seg0) umin0 = fminf(umin0, u); else umin1 = fminf(umin1, u);
        }
    }
    #pragma unroll
    for (int off = 16; off; off >>= 1) {
        umin0 = fminf(umin0, __shfl_xor_sync(0xffffffffu, umin0, off));
        umin1 = fminf(umin1, __shfl_xor_sync(0xffffffffu, umin1, off));
    }
    float b0 = w_raw(tab, mg + fminf(umin0, 1023.5f), mg, ec0);
    float b1 = w_raw(tab, mg + fminf(umin1, 1023.5f), mg, ec1);
    float bound = fmaxf(fmaxf(b0, b1), 1.0f);
    float invb = 1.0f / bound;

    // pass B: interp + quantize + sum of quantized
    float sum = 0.f;
    #pragma unroll 2
    for (int it = 0; it < 32; it++) {
        int n0 = it * 128 + lane * 4;
        float4 t4 = *(const float4*)&ts[n0];
        int rl = (n0 < L_SZ) ? rl0 : rl1;
        float ec = (n0 < L_SZ) ? ec0 : ec1;
        float w[4];
        #pragma unroll
        for (int q = 0; q < 4; q++) {
            float tm = (q == 0) ? t4.x : (q == 1) ? t4.y : (q == 2) ? t4.z : t4.w;
            float wr = w_raw(tab, tm, mg, ec);
            bool valid = ((n0 + q) & 2047) < rl;
            w[q] = valid ? wr * invb : 0.f;
        }
        __half2 p0 = __floats2half2_rn(w[0], w[1]);
        __half2 p1 = __floats2half2_rn(w[2], w[3]);
        float2 f0 = __half22float2(p0);
        float2 f1 = __half22float2(p1);
        sum += (f0.x + f0.y) + (f1.x + f1.y);
        uint2 pk = make_uint2(*(uint32_t*)&p0, *(uint32_t*)&p1);
        *(uint2*)&g_w[base + n0] = pk;
    }
    #pragma unroll
    for (int off = 16; off; off >>= 1) sum += __shfl_xor_sync(0xffffffffu, sum, off);
    if (lane == 0) g_sc[b * G_SZ + g] = 1.0f / sum;
}

// ---------------- fp16 mma.sync GEMM: 128x128 tiles, 2 CTAs/SM ----------------
#define KTILE 32
#define STAGES 4
#define ROWB 80                        // padded row stride (bytes)
#define A_TILE_B (128 * ROWB)          // 10240
#define STG_B (2 * A_TILE_B)           // 20480

__global__ void __launch_bounds__(256, 2) k_gemm(float* __restrict__ out) {
    extern __shared__ char smG[];
    uint32_t smb = smem_u32(smG);
    float* smInv = (float*)(smG + STAGES * STG_B);
    int tid = threadIdx.x, wid = tid >> 5, lane = tid & 31;
    int b  = blockIdx.z;
    int g0 = blockIdx.x * 128;
    int d0 = blockIdx.y * 128;
    int wm = wid >> 2, wn = wid & 3;          // 2 x 4 warps; warp tile 64g x 32d

    if (tid < 128) smInv[tid] = g_sc[b * G_SZ + g0 + tid];

    const __half* wbase = g_w + (((uint32_t)(b * G_SZ + g0)) << 12);
    const __half* ebase = g_e + (((uint32_t)(b * D_EMBD + d0)) << 12);

    auto load_stage = [&](int s, int k0) {
        uint32_t st = smb + s * STG_B;
        #pragma unroll
        for (int t = 0; t < 2; t++) {           // A: 128 rows x 4 chunks
            int id = tid + t * 256;
            int row = id >> 2, c = id & 3;
            cp16(st + row * ROWB + c * 16, wbase + ((uint32_t)row << 12) + k0 + c * 8);
        }
        #pragma unroll
        for (int t = 0; t < 2; t++) {           // B: 128 rows x 4 chunks
            int id = tid + t * 256;
            int row = id >> 2, c = id & 3;
            cp16(st + A_TILE_B + row * ROWB + c * 16,
                 ebase + ((uint32_t)row << 12) + k0 + c * 8);
        }
        asm volatile("cp.async.commit_group;" ::: "memory");
    };

    float acc[4][4][4];
    #pragma unroll
    for (int i = 0; i < 4; i++)
        #pragma unroll
        for (int j = 0; j < 4; j++)
            #pragma unroll
            for (int q = 0; q < 4; q++) acc[i][j][q] = 0.f;

    load_stage(0, 0);
    load_stage(1, KTILE);
    load_stage(2, 2 * KTILE);

    int a_row = (lane & 7) + ((lane >> 3) & 1) * 8;
    int a_col = (lane >> 4) * 16;
    int b_grp = lane >> 3;
    int b_row = (b_grp >> 1) * 8 + (lane & 7);
    int b_col = (b_grp & 1) * 16;

    for (int i = 0; i < 128; i++) {
        if (i <= 125)      asm volatile("cp.async.wait_group 2;" ::: "memory");
        else if (i == 126) asm volatile("cp.async.wait_group 1;" ::: "memory");
        else               asm volatile("cp.async.wait_group 0;" ::: "memory");
        __syncthreads();

        uint32_t abase = smb + (i & 3) * STG_B;
        uint32_t bbase = abase + A_TILE_B;
        #pragma unroll
        for (int ks = 0; ks < 2; ks++) {
            uint32_t af[4][4], bf[2][4];
            #pragma unroll
            for (int m = 0; m < 4; m++)
                ldm_x4(af[m], abase + (wm * 64 + m * 16 + a_row) * ROWB + ks * 32 + a_col);
            #pragma unroll
            for (int jp = 0; jp < 2; jp++)
                ldm_x4(bf[jp], bbase + (wn * 32 + jp * 16 + b_row) * ROWB + ks * 32 + b_col);
            #pragma unroll
            for (int m = 0; m < 4; m++)
                #pragma unroll
                for (int j = 0; j < 4; j++)
                    mma16816(acc[m][j], af[m], bf[j >> 1][(j & 1) * 2], bf[j >> 1][(j & 1) * 2 + 1]);
        }
        if (i < 125) load_stage((i + 3) & 3, (i + 3) * KTILE);
    }

    #pragma unroll
    for (int m = 0; m < 4; m++) {
        int r0 = wm * 64 + m * 16 + (lane >> 2);
        float sc0 = smInv[r0], sc1 = smInv[r0 + 8];
        uint32_t gr0 = (uint32_t)(b * G_SZ + g0 + r0) * D_EMBD + d0 + wn * 32;
        #pragma unroll
        for (int j = 0; j < 4; j++) {
            int col = j * 8 + (lane & 3) * 2;
            *(float2*)(out + gr0 + col) =
                make_float2(acc[m][j][0] * sc0, acc[m][j][1] * sc0);
            *(float2*)(out + gr0 + 8 * D_EMBD + col) =
                make_float2(acc[m][j][2] * sc1, acc[m][j][3] * sc1);
        }
    }
}

// ---------------- launch ----------------
extern "C" void kernel_launch(void* const* d_in, const int* in_sizes, int n_in,
                              void* d_out, int out_size) {
    const float* times    = (const float*)d_in[0];
    const float* type_emb = (const float*)d_in[1];
    const int*   real_len = (const int*)d_in[2];
    float* out = (float*)d_out;
    (void)in_sizes; (void)n_in; (void)out_size;

    size_t smem_w = (size_t)(2 * (TAB_N + 1) + 2 + N_EV) * sizeof(float);    // ~80 KB
    size_t smem_g = STAGES * STG_B + 128 * sizeof(float);                    // ~82.4 KB
    cudaFuncSetAttribute(k_weights, cudaFuncAttributeMaxDynamicSharedMemorySize, (int)smem_w);
    cudaFuncSetAttribute(k_gemm,    cudaFuncAttributeMaxDynamicSharedMemorySize, (int)smem_g);

    k_omega<<<1, NPAIR>>>();
    k_table<<<TAB_N + 1, 256>>>();
    k_ec<<<dim3(G_SZ, T_TYPES), 256>>>(type_emb);
    k_emb_t<<<dim3(N_EV / 32, B_SZ), 256>>>(times, type_emb);
    k_weights<<<dim3(G_SZ / 16, B_SZ), 512, smem_w>>>(times, real_len);
    k_gemm<<<dim3(G_SZ / 128, D_EMBD / 128, B_SZ), 256, smem_g>>>(out);
}

// round 7
// speedup vs baseline: 7.5959x; 1.1750x over previous
#include <cuda_runtime.h>
#include <cuda_fp16.h>
#include <math.h>
#include <stdint.h>

#define T_TYPES 2
#define B_SZ 16
#define L_SZ 2048
#define N_EV 4096          // T*L
#define D_EMBD 512
#define G_SZ 1024
#define NPAIR 256          // D/2
#define TAB_N 4096         // symmetric table, u in [0,1024], h = 1/4
#define INV_SQRT_D 0.04419417382415922f

// ---------------- device scratch ----------------
__device__ double g_omega[NPAIR];
__device__ float  g_omf[NPAIR];
__device__ float2 g_tab[TAB_N + 1];                  // (H(u), H'(u)*h)
__device__ float4 g_tab4[TAB_N];                     // (H_j, Hd_j, H_{j+1}, Hd_{j+1})
__device__ float  g_ec[T_TYPES * G_SZ];              // exp(type_emb . q[g] / sqrt(D))
__device__ float  g_sc[B_SZ * G_SZ];                 // 1 / sum(stored w)
__device__ __align__(128) __half g_w[(size_t)B_SZ * G_SZ * N_EV];   // 128MB
__device__ __align__(128) __half g_e[(size_t)B_SZ * D_EMBD * N_EV]; // 64MB

// ---------------- helpers ----------------
__device__ __forceinline__ uint32_t smem_u32(const void* p) {
    uint32_t a;
    asm("{ .reg .u64 t; cvta.to.shared.u64 t, %1; cvt.u32.u64 %0, t; }" : "=r"(a) : "l"(p));
    return a;
}
__device__ __forceinline__ void cp16(uint32_t dst, const void* src) {
    asm volatile("cp.async.cg.shared.global [%0], [%1], 16;" :: "r"(dst), "l"(src));
}
__device__ __forceinline__ void ldm_x4(uint32_t (&r)[4], uint32_t addr) {
    asm volatile("ldmatrix.sync.aligned.m8n8.x4.shared.b16 {%0,%1,%2,%3}, [%4];"
                 : "=r"(r[0]), "=r"(r[1]), "=r"(r[2]), "=r"(r[3]) : "r"(addr));
}
__device__ __forceinline__ void mma16816(float (&c)[4], const uint32_t (&a)[4],
                                         uint32_t b0, uint32_t b1) {
    asm volatile("mma.sync.aligned.m16n8k16.row.col.f32.f16.f16.f32 "
                 "{%0,%1,%2,%3}, {%4,%5,%6,%7}, {%8,%9}, {%0,%1,%2,%3};"
                 : "+f"(c[0]), "+f"(c[1]), "+f"(c[2]), "+f"(c[3])
                 : "r"(a[0]), "r"(a[1]), "r"(a[2]), "r"(a[3]), "r"(b0), "r"(b1));
}
__device__ __forceinline__ float reduce_angle(double phase) {
    const double TWO_PI  = 6.283185307179586476925286766559;
    const double INV_2PI = 0.15915494309189533576888376337251;
    double k = rint(phase * INV_2PI);
    return (float)fma(-k, TWO_PI, phase);
}
// fp32 Cody-Waite range reduction: x in [0, 1024], |r| <= pi
__device__ __forceinline__ float reduce_f32(float x) {
    const float INV2PI = 0.15915494309189535f;
    const float C1 = 6.28125f;
    const float C2 = 1.9353071795864769e-3f;
    float kf = rintf(x * INV2PI);
    float r = fmaf(-kf, C1, x);
    return fmaf(-kf, C2, r);
}

// ---------------- setup kernels ----------------
__global__ void k_omega() {
    int i = threadIdx.x;
    double om = pow(10000.0, -(double)i / 256.0);
    g_omega[i] = om;
    g_omf[i] = (float)om;
}

__global__ void k_table() {
    __shared__ float rc[256], rs[256];
    int j = blockIdx.x, i = threadIdx.x;
    double u = (double)j * 0.25;
    double om = g_omega[i];
    float r = reduce_angle(u * om);
    float s, c; __sincosf(r, &s, &c);
    rc[i] = c;
    rs[i] = (float)om * s;
    __syncthreads();
    #pragma unroll
    for (int st = 128; st > 0; st >>= 1) {
        if (i < st) { rc[i] += rc[i + st]; rs[i] += rs[i + st]; }
        __syncthreads();
    }
    if (i == 0) {
        float H  = expf(rc[0] * INV_SQRT_D);
        float Hp = -H * rs[0] * INV_SQRT_D;
        g_tab[j] = make_float2(H, Hp * 0.25f);
    }
}

__global__ void k_pack() {
    int j = blockIdx.x * 256 + threadIdx.x;
    if (j < TAB_N) {
        float2 a = g_tab[j], b = g_tab[j + 1];
        g_tab4[j] = make_float4(a.x, a.y, b.x, b.y);
    }
}

__global__ void k_ec(const float* __restrict__ type_emb) {
    __shared__ float red[256];
    int g = blockIdx.x, t = blockIdx.y, i = threadIdx.x;
    float r = reduce_angle(((double)g + 0.5) * g_omega[i]);
    float s, c; __sincosf(r, &s, &c);
    red[i] = type_emb[t * D_EMBD + 2 * i] * s + type_emb[t * D_EMBD + 2 * i + 1] * c;
    __syncthreads();
    #pragma unroll
    for (int st = 128; st > 0; st >>= 1) { if (i < st) red[i] += red[i + st]; __syncthreads(); }
    if (i == 0) g_ec[t * G_SZ + g] = expf(red[0] * INV_SQRT_D);
}

// emb to [b][d][n] fp16 — no smem, no fp64
__global__ void __launch_bounds__(256) k_emb_t(const float* __restrict__ times,
                                               const float* __restrict__ type_emb) {
    int lane = threadIdx.x & 31, w = threadIdx.x >> 5;
    int b = blockIdx.y;
    int n0 = blockIdx.x * 32;
    int tIdx = n0 >> 11;
    int l = (n0 + lane) & 2047;
    float tm = times[(size_t)tIdx * (B_SZ * L_SZ) + (size_t)b * L_SZ + l];
    bool nz = (tm != 0.f);
    uint32_t base = (uint32_t)b * (D_EMBD * N_EV) + n0 + lane;
    #pragma unroll 4
    for (int ii = 0; ii < 32; ii++) {
        int i = w + ii * 8;
        float x = tm * g_omf[i];
        float r = reduce_f32(x);
        float s, c; __sincosf(r, &s, &c);
        float2 te = *(const float2*)&type_emb[tIdx * D_EMBD + 2 * i];
        __half h0 = __float2half_rn(nz ? s + te.x : 0.f);
        __half h1 = __float2half_rn(nz ? c + te.y : 0.f);
        g_e[base + (uint32_t)(2 * i) * N_EV]     = h0;
        g_e[base + (uint32_t)(2 * i + 1) * N_EV] = h1;
    }
}

// unnormalized weight: cubic Hermite, single aligned LDS.128 per interp
__device__ __forceinline__ float w_raw4(const float4* tab, float tm, float mg, float ec) {
    float u  = fabsf(tm - mg);
    float x  = u * 4.f;
    float xf = floorf(x);
    int idx  = (int)xf;
    float fr = x - xf;
    float4 T = tab[idx];               // (H0, Hd0, H1, Hd1)
    float d  = T.z - T.x;
    float qa = 3.f * d - 2.f * T.y - T.w;
    float qb = T.y + T.w - 2.f * d;
    float p  = fmaf(fr, fmaf(fr, fmaf(fr, qb, qa), T.y), T.x);
    return (tm != 0.f) ? p * ec : 1.0f;
}

// single interp pass with min-distance bound pre-pass (registers only)
__global__ void __launch_bounds__(512) k_weights(const float* __restrict__ times,
                                                 const int* __restrict__ real_len) {
    extern __shared__ float smW[];
    float4* tab = (float4*)smW;                     // TAB_N float4 (64KB)
    float*  ts  = smW + 4 * TAB_N;                  // N_EV floats
    int tid = threadIdx.x;                          // 512
    int b = blockIdx.y;
    for (int j = tid; j < TAB_N; j += 512) tab[j] = g_tab4[j];
    for (int j = tid; j < N_EV; j += 512) {
        int tI = j >> 11, l = j & 2047;
        ts[j] = times[(size_t)tI * (B_SZ * L_SZ) + (size_t)b * L_SZ + l];
    }
    __syncthreads();
    int rl0 = real_len[b], rl1 = real_len[B_SZ + b];
    int warp = tid >> 5, lane = tid & 31;
    int g = blockIdx.x * 16 + warp;
    float ec0 = g_ec[g], ec1 = g_ec[G_SZ + g];
    float mg = (float)g + 0.5f;
    uint32_t base = ((uint32_t)(b * G_SZ + g)) << 12;

    // pass A: per-segment min distance among valid nonzero-time events
    float umin0 = 1e9f, umin1 = 1e9f;
    #pragma unroll 2
    for (int it = 0; it < 32; it++) {
        int n0 = it * 128 + lane * 4;
        float4 t4 = *(const float4*)&ts[n0];
        int rl = (n0 < L_SZ) ? rl0 : rl1;
        bool seg0 = (n0 < L_SZ);
        #pragma unroll
        for (int q = 0; q < 4; q++) {
            float tm = (q == 0) ? t4.x : (q == 1) ? t4.y : (q == 2) ? t4.z : t4.w;
            bool valid = (((n0 + q) & 2047) < rl) && (tm != 0.f);
            float u = valid ? fabsf(tm - mg) : 1e9f;
            if (seg0) umin0 = fminf(umin0, u); else umin1 = fminf(umin1, u);
        }
    }
    #pragma unroll
    for (int off = 16; off; off >>= 1) {
        umin0 = fminf(umin0, __shfl_xor_sync(0xffffffffu, umin0, off));
        umin1 = fminf(umin1, __shfl_xor_sync(0xffffffffu, umin1, off));
    }
    float b0 = w_raw4(tab, mg + fminf(umin0, 1023.5f), mg, ec0);
    float b1 = w_raw4(tab, mg + fminf(umin1, 1023.5f), mg, ec1);
    float bound = fmaxf(fmaxf(b0, b1), 1.0f);
    float invb = 1.0f / bound;

    // pass B: interp + quantize + fp32 sum of quantized values
    float sum = 0.f;
    #pragma unroll 2
    for (int it = 0; it < 32; it++) {
        int n0 = it * 128 + lane * 4;
        float4 t4 = *(const float4*)&ts[n0];
        int rl = (n0 < L_SZ) ? rl0 : rl1;
        float ec = (n0 < L_SZ) ? ec0 : ec1;
        float w[4];
        #pragma unroll
        for (int q = 0; q < 4; q++) {
            float tm = (q == 0) ? t4.x : (q == 1) ? t4.y : (q == 2) ? t4.z : t4.w;
            float wr = w_raw4(tab, tm, mg, ec);
            bool valid = ((n0 + q) & 2047) < rl;
            w[q] = valid ? wr * invb : 0.f;
        }
        __half2 p0 = __floats2half2_rn(w[0], w[1]);
        __half2 p1 = __floats2half2_rn(w[2], w[3]);
        float2 f0 = __half22float2(p0);
        float2 f1 = __half22float2(p1);
        sum += (f0.x + f0.y) + (f1.x + f1.y);
        uint2 pk = make_uint2(*(uint32_t*)&p0, *(uint32_t*)&p1);
        *(uint2*)&g_w[base + n0] = pk;
    }
    #pragma unroll
    for (int off = 16; off; off >>= 1) sum += __shfl_xor_sync(0xffffffffu, sum, off);
    if (lane == 0) g_sc[b * G_SZ + g] = 1.0f / sum;
}

// ---------------- fp16 mma.sync GEMM: 128x128 tiles, KTILE=64, swizzled ----------------
#define KT 64
#define STAGES 3
#define A_TILE_B (128 * 128)           // 16384 (128 rows x 128B)
#define STG_B (2 * A_TILE_B)           // 32768

__global__ void __launch_bounds__(256, 2) k_gemm(float* __restrict__ out) {
    extern __shared__ char smG[];
    uint32_t smb = smem_u32(smG);
    float* smInv = (float*)(smG + STAGES * STG_B);
    int tid = threadIdx.x, wid = tid >> 5, lane = tid & 31;
    int b  = blockIdx.z;
    int g0 = blockIdx.x * 128;
    int d0 = blockIdx.y * 128;
    int wm = wid >> 2, wn = wid & 3;          // 2 x 4 warps; warp tile 64g x 32d

    if (tid < 128) smInv[tid] = g_sc[b * G_SZ + g0 + tid];

    const __half* wbase = g_w + (((uint32_t)(b * G_SZ + g0)) << 12);
    const __half* ebase = g_e + (((uint32_t)(b * D_EMBD + d0)) << 12);

    // cp.async swizzled store offsets: col = (c*16) ^ ((row&7)*16)
    auto load_stage = [&](int s, int k0) {
        uint32_t st = smb + s * STG_B;
        #pragma unroll
        for (int t = 0; t < 4; t++) {           // A: 128 rows x 8 chunks
            int id = tid + t * 256;
            int row = id >> 3, c = id & 7;
            uint32_t col = (uint32_t)(c * 16) ^ (uint32_t)((row & 7) << 4);
            cp16(st + row * 128 + col, wbase + ((uint32_t)row << 12) + k0 + c * 8);
        }
        #pragma unroll
        for (int t = 0; t < 4; t++) {           // B: 128 rows x 8 chunks
            int id = tid + t * 256;
            int row = id >> 3, c = id & 7;
            uint32_t col = (uint32_t)(c * 16) ^ (uint32_t)((row & 7) << 4);
            cp16(st + A_TILE_B + row * 128 + col, ebase + ((uint32_t)row << 12) + k0 + c * 8);
        }
        asm volatile("cp.async.commit_group;" ::: "memory");
    };

    float acc[4][4][4];
    #pragma unroll
    for (int i = 0; i < 4; i++)
        #pragma unroll
        for (int j = 0; j < 4; j++)
            #pragma unroll
            for (int q = 0; q < 4; q++) acc[i][j][q] = 0.f;

    load_stage(0, 0);
    load_stage(1, KT);

    int a_row = (lane & 7) + ((lane >> 3) & 1) * 8;
    int a_col = (lane >> 4) * 16;
    int b_grp = lane >> 3;
    int b_row = (b_grp >> 1) * 8 + (lane & 7);
    int b_col = (b_grp & 1) * 16;
    uint32_t lxor = (uint32_t)((lane & 7) << 4);   // row&7 == lane&7 for both A and B

    for (int i = 0; i < 64; i++) {
        if (i < 63) asm volatile("cp.async.wait_group 1;" ::: "memory");
        else        asm volatile("cp.async.wait_group 0;" ::: "memory");
        __syncthreads();

        int s = i % 3;
        uint32_t abase = smb + s * STG_B;
        uint32_t bbase = abase + A_TILE_B;
        #pragma unroll
        for (int ks = 0; ks < 4; ks++) {
            uint32_t acol = ((uint32_t)(ks * 32 + a_col)) ^ lxor;
            uint32_t bcol = ((uint32_t)(ks * 32 + b_col)) ^ lxor;
            uint32_t af[4][4], bf[2][4];
            #pragma unroll
            for (int m = 0; m < 4; m++)
                ldm_x4(af[m], abase + (wm * 64 + m * 16 + a_row) * 128 + acol);
            #pragma unroll
            for (int jp = 0; jp < 2; jp++)
                ldm_x4(bf[jp], bbase + (wn * 32 + jp * 16 + b_row) * 128 + bcol);
            #pragma unroll
            for (int m = 0; m < 4; m++)
                #pragma unroll
                for (int j = 0; j < 4; j++)
                    mma16816(acc[m][j], af[m], bf[j >> 1][(j & 1) * 2], bf[j >> 1][(j & 1) * 2 + 1]);
        }
        if (i + 2 < 64) load_stage((i + 2) % 3, (i + 2) * KT);
    }

    #pragma unroll
    for (int m = 0; m < 4; m++) {
        int r0 = wm * 64 + m * 16 + (lane >> 2);
        float sc0 = smInv[r0], sc1 = smInv[r0 + 8];
        uint32_t gr0 = (uint32_t)(b * G_SZ + g0 + r0) * D_EMBD + d0 + wn * 32;
        #pragma unroll
        for (int j = 0; j < 4; j++) {
            int col = j * 8 + (lane & 3) * 2;
            *(float2*)(out + gr0 + col) =
                make_float2(acc[m][j][0] * sc0, acc[m][j][1] * sc0);
            *(float2*)(out + gr0 + 8 * D_EMBD + col) =
                make_float2(acc[m][j][2] * sc1, acc[m][j][3] * sc1);
        }
    }
}

// ---------------- launch ----------------
extern "C" void kernel_launch(void* const* d_in, const int* in_sizes, int n_in,
                              void* d_out, int out_size) {
    const float* times    = (const float*)d_in[0];
    const float* type_emb = (const float*)d_in[1];
    const int*   real_len = (const int*)d_in[2];
    float* out = (float*)d_out;
    (void)in_sizes; (void)n_in; (void)out_size;

    size_t smem_w = (size_t)(4 * TAB_N + N_EV) * sizeof(float);              // 80 KB
    size_t smem_g = STAGES * STG_B + 128 * sizeof(float);                    // ~96.5 KB
    cudaFuncSetAttribute(k_weights, cudaFuncAttributeMaxDynamicSharedMemorySize, (int)smem_w);
    cudaFuncSetAttribute(k_gemm,    cudaFuncAttributeMaxDynamicSharedMemorySize, (int)smem_g);

    k_omega<<<1, NPAIR>>>();
    k_table<<<TAB_N + 1, 256>>>();
    k_pack<<<(TAB_N + 255) / 256, 256>>>();
    k_ec<<<dim3(G_SZ, T_TYPES), 256>>>(type_emb);
    k_emb_t<<<dim3(N_EV / 32, B_SZ), 256>>>(times, type_emb);
    k_weights<<<dim3(G_SZ / 16, B_SZ), 512, smem_w>>>(times, real_len);
    k_gemm<<<dim3(G_SZ / 128, D_EMBD / 128, B_SZ), 256, smem_g>>>(out);
}

// round 8
// speedup vs baseline: 11.5523x; 1.5209x over previous
#include <cuda_runtime.h>
#include <cuda_fp16.h>
#include <math.h>
#include <stdint.h>

#define T_TYPES 2
#define B_SZ 16
#define L_SZ 2048
#define N_EV 4096          // T*L
#define D_EMBD 512
#define G_SZ 1024
#define NPAIR 256          // D/2
#define TAB_N 4096         // symmetric table, u in [0,1024], h = 1/4
#define INV_SQRT_D 0.04419417382415922f

// ---------------- device scratch ----------------
__device__ double g_omega[NPAIR];
__device__ float  g_omf[NPAIR];
__device__ float2 g_tab[TAB_N + 1];                  // (H(u), H'(u)*h)
__device__ float4 g_tab4[TAB_N];                     // (H_j, Hd_j, H_{j+1}, Hd_{j+1})
__device__ float  g_ec[T_TYPES * G_SZ];              // exp(type_emb . q[g] / sqrt(D))
__device__ float  g_sc[B_SZ * G_SZ];                 // 1 / sum(stored w)
__device__ __align__(128) __half g_w[(size_t)B_SZ * G_SZ * N_EV];   // 128MB
__device__ __align__(128) __half g_e[(size_t)B_SZ * D_EMBD * N_EV]; // 64MB

// ---------------- helpers ----------------
__device__ __forceinline__ uint32_t smem_u32(const void* p) {
    uint32_t a;
    asm("{ .reg .u64 t; cvta.to.shared.u64 t, %1; cvt.u32.u64 %0, t; }" : "=r"(a) : "l"(p));
    return a;
}
__device__ __forceinline__ void cp16(uint32_t dst, const void* src) {
    asm volatile("cp.async.cg.shared.global [%0], [%1], 16;" :: "r"(dst), "l"(src));
}
__device__ __forceinline__ void ldm_x4(uint32_t (&r)[4], uint32_t addr) {
    asm volatile("ldmatrix.sync.aligned.m8n8.x4.shared.b16 {%0,%1,%2,%3}, [%4];"
                 : "=r"(r[0]), "=r"(r[1]), "=r"(r[2]), "=r"(r[3]) : "r"(addr));
}
__device__ __forceinline__ void mma16816(float (&c)[4], const uint32_t (&a)[4],
                                         uint32_t b0, uint32_t b1) {
    asm volatile("mma.sync.aligned.m16n8k16.row.col.f32.f16.f16.f32 "
                 "{%0,%1,%2,%3}, {%4,%5,%6,%7}, {%8,%9}, {%0,%1,%2,%3};"
                 : "+f"(c[0]), "+f"(c[1]), "+f"(c[2]), "+f"(c[3])
                 : "r"(a[0]), "r"(a[1]), "r"(a[2]), "r"(a[3]), "r"(b0), "r"(b1));
}
__device__ __forceinline__ float reduce_angle(double phase) {
    const double TWO_PI  = 6.283185307179586476925286766559;
    const double INV_2PI = 0.15915494309189533576888376337251;
    double k = rint(phase * INV_2PI);
    return (float)fma(-k, TWO_PI, phase);
}
// fp32 Cody-Waite range reduction: x in [0, 1024], |r| <= pi
__device__ __forceinline__ float reduce_f32(float x) {
    const float INV2PI = 0.15915494309189535f;
    const float C1 = 6.28125f;
    const float C2 = 1.9353071795864769e-3f;
    float kf = rintf(x * INV2PI);
    float r = fmaf(-kf, C1, x);
    return fmaf(-kf, C2, r);
}

// ---------------- setup kernels ----------------
__global__ void k_omega() {
    int i = threadIdx.x;
    double om = pow(10000.0, -(double)i / 256.0);
    g_omega[i] = om;
    g_omf[i] = (float)om;
}

// warp per table entry
__global__ void k_table() {
    int lane = threadIdx.x & 31;
    int j = (blockIdx.x * blockDim.x + threadIdx.x) >> 5;
    if (j > TAB_N) return;
    double u = (double)j * 0.25;
    float rc = 0.f, rs = 0.f;
    #pragma unroll
    for (int q = 0; q < 8; q++) {
        int i = lane + q * 32;
        double om = g_omega[i];
        float r = reduce_angle(u * om);
        float s, c; __sincosf(r, &s, &c);
        rc += c;
        rs += (float)om * s;
    }
    #pragma unroll
    for (int off = 16; off; off >>= 1) {
        rc += __shfl_xor_sync(0xffffffffu, rc, off);
        rs += __shfl_xor_sync(0xffffffffu, rs, off);
    }
    if (lane == 0) {
        float H  = expf(rc * INV_SQRT_D);
        float Hp = -H * rs * INV_SQRT_D;
        g_tab[j] = make_float2(H, Hp * 0.25f);
    }
}

__global__ void k_pack() {
    int j = blockIdx.x * 256 + threadIdx.x;
    if (j < TAB_N) {
        float2 a = g_tab[j], b = g_tab[j + 1];
        g_tab4[j] = make_float4(a.x, a.y, b.x, b.y);
    }
}

// warp per (t,g)
__global__ void k_ec(const float* __restrict__ type_emb) {
    int lane = threadIdx.x & 31;
    int e = (blockIdx.x * blockDim.x + threadIdx.x) >> 5;   // 0..2047
    int t = e >> 10, g = e & 1023;
    double m = (double)g + 0.5;
    float acc = 0.f;
    #pragma unroll
    for (int q = 0; q < 8; q++) {
        int i = lane + q * 32;
        float r = reduce_angle(m * g_omega[i]);
        float s, c; __sincosf(r, &s, &c);
        acc += type_emb[t * D_EMBD + 2 * i] * s + type_emb[t * D_EMBD + 2 * i + 1] * c;
    }
    #pragma unroll
    for (int off = 16; off; off >>= 1) acc += __shfl_xor_sync(0xffffffffu, acc, off);
    if (lane == 0) g_ec[t * G_SZ + g] = expf(acc * INV_SQRT_D);
}

// emb to [b][d][n] fp16 — skip blocks beyond the valid 64-tile bound
__global__ void __launch_bounds__(256) k_emb_t(const float* __restrict__ times,
                                               const float* __restrict__ type_emb,
                                               const int* __restrict__ real_len) {
    int b = blockIdx.y;
    int n0 = blockIdx.x * 32;
    int tIdx = n0 >> 11;
    int rl = real_len[tIdx * B_SZ + b];
    int K = (rl + 63) & ~63;
    if ((n0 & 2047) >= K) return;
    int lane = threadIdx.x & 31, w = threadIdx.x >> 5;
    int l = (n0 + lane) & 2047;
    float tm = times[(size_t)tIdx * (B_SZ * L_SZ) + (size_t)b * L_SZ + l];
    bool nz = (tm != 0.f);
    uint32_t base = (uint32_t)b * (D_EMBD * N_EV) + n0 + lane;
    #pragma unroll 4
    for (int ii = 0; ii < 32; ii++) {
        int i = w + ii * 8;
        float x = tm * g_omf[i];
        float r = reduce_f32(x);
        float s, c; __sincosf(r, &s, &c);
        float2 te = *(const float2*)&type_emb[tIdx * D_EMBD + 2 * i];
        __half h0 = __float2half_rn(nz ? s + te.x : 0.f);
        __half h1 = __float2half_rn(nz ? c + te.y : 0.f);
        g_e[base + (uint32_t)(2 * i) * N_EV]     = h0;
        g_e[base + (uint32_t)(2 * i + 1) * N_EV] = h1;
    }
}

// unnormalized weight: cubic Hermite, single aligned LDS.128 per interp
__device__ __forceinline__ float w_raw4(const float4* tab, float tm, float mg, float ec) {
    float u  = fabsf(tm - mg);
    float x  = u * 4.f;
    float xf = floorf(x);
    int idx  = (int)xf;
    float fr = x - xf;
    float4 T = tab[idx];               // (H0, Hd0, H1, Hd1)
    float d  = T.z - T.x;
    float qa = 3.f * d - 2.f * T.y - T.w;
    float qb = T.y + T.w - 2.f * d;
    float p  = fmaf(fr, fmaf(fr, fmaf(fr, qb, qa), T.y), T.x);
    return (tm != 0.f) ? p * ec : 1.0f;
}

// weights over valid ranges only (zero-padded to the 64-tile boundary)
__global__ void __launch_bounds__(512) k_weights(const float* __restrict__ times,
                                                 const int* __restrict__ real_len) {
    extern __shared__ float smW[];
    float4* tab = (float4*)smW;                     // TAB_N float4 (64KB)
    float*  ts  = smW + 4 * TAB_N;                  // N_EV floats
    int tid = threadIdx.x;                          // 512
    int b = blockIdx.y;
    int rl0 = real_len[b], rl1 = real_len[B_SZ + b];
    int K0 = (rl0 + 63) & ~63, K1 = (rl1 + 63) & ~63;
    for (int j = tid; j < TAB_N; j += 512) tab[j] = g_tab4[j];
    for (int j = tid; j < K0; j += 512)
        ts[j] = times[(size_t)b * L_SZ + j];
    for (int j = tid; j < K1; j += 512)
        ts[2048 + j] = times[(size_t)(B_SZ * L_SZ) + (size_t)b * L_SZ + j];
    __syncthreads();
    int warp = tid >> 5, lane = tid & 31;
    int g = blockIdx.x * 16 + warp;
    float ec0 = g_ec[g], ec1 = g_ec[G_SZ + g];
    float mg = (float)g + 0.5f;
    uint32_t base = ((uint32_t)(b * G_SZ + g)) << 12;

    // pass A: min distance among valid nonzero events (registers only)
    float umin0 = 1e9f, umin1 = 1e9f;
    for (int n0 = lane * 4; n0 < K0; n0 += 128) {
        float4 t4 = *(const float4*)&ts[n0];
        #pragma unroll
        for (int q = 0; q < 4; q++) {
            float tm = (q == 0) ? t4.x : (q == 1) ? t4.y : (q == 2) ? t4.z : t4.w;
            bool valid = (n0 + q < rl0) && (tm != 0.f);
            umin0 = fminf(umin0, valid ? fabsf(tm - mg) : 1e9f);
        }
    }
    for (int n0 = lane * 4; n0 < K1; n0 += 128) {
        float4 t4 = *(const float4*)&ts[2048 + n0];
        #pragma unroll
        for (int q = 0; q < 4; q++) {
            float tm = (q == 0) ? t4.x : (q == 1) ? t4.y : (q == 2) ? t4.z : t4.w;
            bool valid = (n0 + q < rl1) && (tm != 0.f);
            umin1 = fminf(umin1, valid ? fabsf(tm - mg) : 1e9f);
        }
    }
    #pragma unroll
    for (int off = 16; off; off >>= 1) {
        umin0 = fminf(umin0, __shfl_xor_sync(0xffffffffu, umin0, off));
        umin1 = fminf(umin1, __shfl_xor_sync(0xffffffffu, umin1, off));
    }
    float b0 = w_raw4(tab, mg + fminf(umin0, 1023.5f), mg, ec0);
    float b1 = w_raw4(tab, mg + fminf(umin1, 1023.5f), mg, ec1);
    float bound = fmaxf(fmaxf(b0, b1), 1.0f);
    float invb = 1.0f / bound;

    // pass B: interp + quantize + fp32 sum of quantized values
    float sum = 0.f;
    #pragma unroll 1
    for (int seg = 0; seg < 2; seg++) {
        int K  = seg ? K1 : K0;
        int rl = seg ? rl1 : rl0;
        float ec = seg ? ec1 : ec0;
        int off_ts = seg ? 2048 : 0;
        for (int n0 = lane * 4; n0 < K; n0 += 128) {
            float4 t4 = *(const float4*)&ts[off_ts + n0];
            float w[4];
            #pragma unroll
            for (int q = 0; q < 4; q++) {
                float tm = (q == 0) ? t4.x : (q == 1) ? t4.y : (q == 2) ? t4.z : t4.w;
                float wr = w_raw4(tab, tm, mg, ec);
                w[q] = (n0 + q < rl) ? wr * invb : 0.f;
            }
            __half2 p0 = __floats2half2_rn(w[0], w[1]);
            __half2 p1 = __floats2half2_rn(w[2], w[3]);
            float2 f0 = __half22float2(p0);
            float2 f1 = __half22float2(p1);
            sum += (f0.x + f0.y) + (f1.x + f1.y);
            uint2 pk = make_uint2(*(uint32_t*)&p0, *(uint32_t*)&p1);
            *(uint2*)&g_w[base + off_ts + n0] = pk;
        }
    }
    #pragma unroll
    for (int off = 16; off; off >>= 1) sum += __shfl_xor_sync(0xffffffffu, sum, off);
    if (lane == 0) g_sc[b * G_SZ + g] = 1.0f / sum;
}

// ---------------- fp16 mma.sync GEMM: ragged K, 128x128 tiles, swizzled ----------------
#define KT 64
#define STAGES 3
#define A_TILE_B (128 * 128)           // 16384 (128 rows x 128B)
#define STG_B (2 * A_TILE_B)           // 32768

__global__ void __launch_bounds__(256, 2) k_gemm(const int* __restrict__ real_len,
                                                 float* __restrict__ out) {
    extern __shared__ char smG[];
    uint32_t smb = smem_u32(smG);
    float* smInv = (float*)(smG + STAGES * STG_B);
    int tid = threadIdx.x, wid = tid >> 5, lane = tid & 31;
    int b  = blockIdx.z;
    int g0 = blockIdx.x * 128;
    int d0 = blockIdx.y * 128;
    int wm = wid >> 2, wn = wid & 3;          // 2 x 4 warps; warp tile 64g x 32d

    int nk0 = (((real_len[b] + 63) & ~63) >> 6);
    int nk1 = (((real_len[B_SZ + b] + 63) & ~63) >> 6);
    int nk  = nk0 + nk1;                      // 2..64

    if (tid < 128) smInv[tid] = g_sc[b * G_SZ + g0 + tid];

    const __half* wbase = g_w + (((uint32_t)(b * G_SZ + g0)) << 12);
    const __half* ebase = g_e + (((uint32_t)(b * D_EMBD + d0)) << 12);

    auto kof = [&](int i) { return i < nk0 ? i * KT : (i - nk0) * KT + 2048; };

    auto load_stage = [&](int s, int k0) {
        uint32_t st = smb + s * STG_B;
        #pragma unroll
        for (int t = 0; t < 4; t++) {           // A: 128 rows x 8 chunks
            int id = tid + t * 256;
            int row = id >> 3, c = id & 7;
            uint32_t col = (uint32_t)(c * 16) ^ (uint32_t)((row & 7) << 4);
            cp16(st + row * 128 + col, wbase + ((uint32_t)row << 12) + k0 + c * 8);
        }
        #pragma unroll
        for (int t = 0; t < 4; t++) {           // B: 128 rows x 8 chunks
            int id = tid + t * 256;
            int row = id >> 3, c = id & 7;
            uint32_t col = (uint32_t)(c * 16) ^ (uint32_t)((row & 7) << 4);
            cp16(st + A_TILE_B + row * 128 + col, ebase + ((uint32_t)row << 12) + k0 + c * 8);
        }
        asm volatile("cp.async.commit_group;" ::: "memory");
    };

    float acc[4][4][4];
    #pragma unroll
    for (int i = 0; i < 4; i++)
        #pragma unroll
        for (int j = 0; j < 4; j++)
            #pragma unroll
            for (int q = 0; q < 4; q++) acc[i][j][q] = 0.f;

    load_stage(0, kof(0));
    load_stage(1, kof(1));

    int a_row = (lane & 7) + ((lane >> 3) & 1) * 8;
    int a_col = (lane >> 4) * 16;
    int b_grp = lane >> 3;
    int b_row = (b_grp >> 1) * 8 + (lane & 7);
    int b_col = (b_grp & 1) * 16;
    uint32_t lxor = (uint32_t)((lane & 7) << 4);

    for (int i = 0; i < nk; i++) {
        if (i < nk - 1) asm volatile("cp.async.wait_group 1;" ::: "memory");
        else            asm volatile("cp.async.wait_group 0;" ::: "memory");
        __syncthreads();

        int s = i % 3;
        uint32_t abase = smb + s * STG_B;
        uint32_t bbase = abase + A_TILE_B;
        #pragma unroll
        for (int ks = 0; ks < 4; ks++) {
            uint32_t acol = ((uint32_t)(ks * 32 + a_col)) ^ lxor;
            uint32_t bcol = ((uint32_t)(ks * 32 + b_col)) ^ lxor;
            uint32_t af[4][4], bf[2][4];
            #pragma unroll
            for (int m = 0; m < 4; m++)
                ldm_x4(af[m], abase + (wm * 64 + m * 16 + a_row) * 128 + acol);
            #pragma unroll
            for (int jp = 0; jp < 2; jp++)
                ldm_x4(bf[jp], bbase + (wn * 32 + jp * 16 + b_row) * 128 + bcol);
            #pragma unroll
            for (int m = 0; m < 4; m++)
                #pragma unroll
                for (int j = 0; j < 4; j++)
                    mma16816(acc[m][j], af[m], bf[j >> 1][(j & 1) * 2], bf[j >> 1][(j & 1) * 2 + 1]);
        }
        if (i + 2 < nk) load_stage((i + 2) % 3, kof(i + 2));
    }

    #pragma unroll
    for (int m = 0; m < 4; m++) {
        int r0 = wm * 64 + m * 16 + (lane >> 2);
        float sc0 = smInv[r0], sc1 = smInv[r0 + 8];
        uint32_t gr0 = (uint32_t)(b * G_SZ + g0 + r0) * D_EMBD + d0 + wn * 32;
        #pragma unroll
        for (int j = 0; j < 4; j++) {
            int col = j * 8 + (lane & 3) * 2;
            *(float2*)(out + gr0 + col) =
                make_float2(acc[m][j][0] * sc0, acc[m][j][1] * sc0);
            *(float2*)(out + gr0 + 8 * D_EMBD + col) =
                make_float2(acc[m][j][2] * sc1, acc[m][j][3] * sc1);
        }
    }
}

// ---------------- launch ----------------
extern "C" void kernel_launch(void* const* d_in, const int* in_sizes, int n_in,
                              void* d_out, int out_size) {
    const float* times    = (const float*)d_in[0];
    const float* type_emb = (const float*)d_in[1];
    const int*   real_len = (const int*)d_in[2];
    float* out = (float*)d_out;
    (void)in_sizes; (void)n_in; (void)out_size;

    size_t smem_w = (size_t)(4 * TAB_N + N_EV) * sizeof(float);              // 80 KB
    size_t smem_g = STAGES * STG_B + 128 * sizeof(float);                    // ~96.5 KB
    cudaFuncSetAttribute(k_weights, cudaFuncAttributeMaxDynamicSharedMemorySize, (int)smem_w);
    cudaFuncSetAttribute(k_gemm,    cudaFuncAttributeMaxDynamicSharedMemorySize, (int)smem_g);

    k_omega<<<1, NPAIR>>>();
    k_table<<<(TAB_N + 8) / 8, 256>>>();                 // warp per entry
    k_pack<<<(TAB_N + 255) / 256, 256>>>();
    k_ec<<<T_TYPES * G_SZ / 8, 256>>>(type_emb);         // warp per (t,g)
    k_emb_t<<<dim3(N_EV / 32, B_SZ), 256>>>(times, type_emb, real_len);
    k_weights<<<dim3(G_SZ / 16, B_SZ), 512, smem_w>>>(times, real_len);
    k_gemm<<<dim3(G_SZ / 128, D_EMBD / 128, B_SZ), 256, smem_g>>>(real_len, out);
}

// round 9
// speedup vs baseline: 12.9432x; 1.1204x over previous
#include <cuda_runtime.h>
#include <cuda_fp16.h>
#include <math.h>
#include <stdint.h>

#define T_TYPES 2
#define B_SZ 16
#define L_SZ 2048
#define N_EV 4096          // T*L
#define D_EMBD 512
#define G_SZ 1024
#define NPAIR 256          // D/2
#define TAB_N 4096         // symmetric table, u in [0,1024], h = 1/4
#define INV_SQRT_D 0.04419417382415922f
#define LOG2_1E4_OVER_256 0.051905126482615036f   // log2(10000)/256

// ---------------- device scratch ----------------
__device__ float  g_omf[NPAIR];
__device__ float4 g_tab4[TAB_N];                     // (H_j, Hd_j, H_{j+1}, Hd_{j+1})
__device__ float  g_ec[T_TYPES * G_SZ];              // exp(type_emb . q[g] / sqrt(D))
__device__ float  g_sc[B_SZ * G_SZ];                 // 1 / sum(stored w)
__device__ __align__(128) __half g_w[(size_t)B_SZ * G_SZ * N_EV];   // 128MB
__device__ __align__(128) __half g_e[(size_t)B_SZ * D_EMBD * N_EV]; // 64MB

// ---------------- helpers ----------------
__device__ __forceinline__ uint32_t smem_u32(const void* p) {
    uint32_t a;
    asm("{ .reg .u64 t; cvta.to.shared.u64 t, %1; cvt.u32.u64 %0, t; }" : "=r"(a) : "l"(p));
    return a;
}
__device__ __forceinline__ void cp16(uint32_t dst, const void* src) {
    asm volatile("cp.async.cg.shared.global [%0], [%1], 16;" :: "r"(dst), "l"(src));
}
__device__ __forceinline__ void ldm_x4(uint32_t (&r)[4], uint32_t addr) {
    asm volatile("ldmatrix.sync.aligned.m8n8.x4.shared.b16 {%0,%1,%2,%3}, [%4];"
                 : "=r"(r[0]), "=r"(r[1]), "=r"(r[2]), "=r"(r[3]) : "r"(addr));
}
__device__ __forceinline__ void mma16816(float (&c)[4], const uint32_t (&a)[4],
                                         uint32_t b0, uint32_t b1) {
    asm volatile("mma.sync.aligned.m16n8k16.row.col.f32.f16.f16.f32 "
                 "{%0,%1,%2,%3}, {%4,%5,%6,%7}, {%8,%9}, {%0,%1,%2,%3};"
                 : "+f"(c[0]), "+f"(c[1]), "+f"(c[2]), "+f"(c[3])
                 : "r"(a[0]), "r"(a[1]), "r"(a[2]), "r"(a[3]), "r"(b0), "r"(b1));
}
// fp32 Cody-Waite range reduction: x in [0, 1024], |r| <= pi
__device__ __forceinline__ float reduce_f32(float x) {
    const float INV2PI = 0.15915494309189535f;
    const float C1 = 6.28125f;
    const float C2 = 1.9353071795864769e-3f;
    float kf = rintf(x * INV2PI);
    float r = fmaf(-kf, C1, x);
    return fmaf(-kf, C2, r);
}

// ---------------- setup kernels (all fp32) ----------------
// warp per table entry; block 0 also publishes g_omf; packs directly into g_tab4
__global__ void k_table() {
    if (blockIdx.x == 0 && threadIdx.x < NPAIR)
        g_omf[threadIdx.x] = exp2f(-(float)threadIdx.x * LOG2_1E4_OVER_256);
    int lane = threadIdx.x & 31;
    int j = (blockIdx.x * blockDim.x + threadIdx.x) >> 5;
    if (j > TAB_N) return;
    float u = (float)j * 0.25f;
    float rc = 0.f, rs = 0.f;
    #pragma unroll
    for (int q = 0; q < 8; q++) {
        int i = lane + q * 32;
        float om = exp2f(-(float)i * LOG2_1E4_OVER_256);
        float r = reduce_f32(u * om);
        float s, c; __sincosf(r, &s, &c);
        rc += c;
        rs += om * s;
    }
    #pragma unroll
    for (int off = 16; off; off >>= 1) {
        rc += __shfl_xor_sync(0xffffffffu, rc, off);
        rs += __shfl_xor_sync(0xffffffffu, rs, off);
    }
    if (lane == 0) {
        float H   = expf(rc * INV_SQRT_D);
        float Hdh = -H * rs * INV_SQRT_D * 0.25f;
        if (j < TAB_N) *(float2*)&g_tab4[j].x     = make_float2(H, Hdh);
        if (j > 0)     *(float2*)&g_tab4[j - 1].z = make_float2(H, Hdh);
    }
}

// warp per (t,g), fp32 phases
__global__ void k_ec(const float* __restrict__ type_emb) {
    int lane = threadIdx.x & 31;
    int e = (blockIdx.x * blockDim.x + threadIdx.x) >> 5;   // 0..2047
    int t = e >> 10, g = e & 1023;
    float mg = (float)g + 0.5f;
    float acc = 0.f;
    #pragma unroll
    for (int q = 0; q < 8; q++) {
        int i = lane + q * 32;
        float om = exp2f(-(float)i * LOG2_1E4_OVER_256);
        float r = reduce_f32(mg * om);
        float s, c; __sincosf(r, &s, &c);
        acc += type_emb[t * D_EMBD + 2 * i] * s + type_emb[t * D_EMBD + 2 * i + 1] * c;
    }
    #pragma unroll
    for (int off = 16; off; off >>= 1) acc += __shfl_xor_sync(0xffffffffu, acc, off);
    if (lane == 0) g_ec[t * G_SZ + g] = expf(acc * INV_SQRT_D);
}

// emb to [b][d][n] fp16 — skip blocks beyond the valid 64-tile bound
__global__ void __launch_bounds__(256) k_emb_t(const float* __restrict__ times,
                                               const float* __restrict__ type_emb,
                                               const int* __restrict__ real_len) {
    int b = blockIdx.y;
    int n0 = blockIdx.x * 32;
    int tIdx = n0 >> 11;
    int rl = real_len[tIdx * B_SZ + b];
    int K = (rl + 63) & ~63;
    if ((n0 & 2047) >= K) return;
    int lane = threadIdx.x & 31, w = threadIdx.x >> 5;
    int l = (n0 + lane) & 2047;
    float tm = times[(size_t)tIdx * (B_SZ * L_SZ) + (size_t)b * L_SZ + l];
    bool nz = (tm != 0.f);
    uint32_t base = (uint32_t)b * (D_EMBD * N_EV) + n0 + lane;
    #pragma unroll 4
    for (int ii = 0; ii < 32; ii++) {
        int i = w + ii * 8;
        float x = tm * g_omf[i];
        float r = reduce_f32(x);
        float s, c; __sincosf(r, &s, &c);
        float2 te = *(const float2*)&type_emb[tIdx * D_EMBD + 2 * i];
        __half h0 = __float2half_rn(nz ? s + te.x : 0.f);
        __half h1 = __float2half_rn(nz ? c + te.y : 0.f);
        g_e[base + (uint32_t)(2 * i) * N_EV]     = h0;
        g_e[base + (uint32_t)(2 * i + 1) * N_EV] = h1;
    }
}

// unnormalized weight: cubic Hermite, single aligned LDS.128 per interp
__device__ __forceinline__ float w_raw4(const float4* tab, float tm, float mg, float ec) {
    float u  = fabsf(tm - mg);
    float x  = u * 4.f;
    float xf = floorf(x);
    int idx  = (int)xf;
    float fr = x - xf;
    float4 T = tab[idx];               // (H0, Hd0, H1, Hd1)
    float d  = T.z - T.x;
    float qa = 3.f * d - 2.f * T.y - T.w;
    float qb = T.y + T.w - 2.f * d;
    float p  = fmaf(fr, fmaf(fr, fmaf(fr, qb, qa), T.y), T.x);
    return (tm != 0.f) ? p * ec : 1.0f;
}

// weights over valid ranges only (zero-padded to the 64-tile boundary)
__global__ void __launch_bounds__(512) k_weights(const float* __restrict__ times,
                                                 const int* __restrict__ real_len) {
    extern __shared__ float smW[];
    float4* tab = (float4*)smW;                     // TAB_N float4 (64KB)
    float*  ts  = smW + 4 * TAB_N;                  // N_EV floats
    int tid = threadIdx.x;                          // 512
    int b = blockIdx.y;
    int rl0 = real_len[b], rl1 = real_len[B_SZ + b];
    int K0 = (rl0 + 63) & ~63, K1 = (rl1 + 63) & ~63;
    for (int j = tid; j < TAB_N; j += 512) tab[j] = g_tab4[j];
    for (int j = tid; j < K0; j += 512)
        ts[j] = times[(size_t)b * L_SZ + j];
    for (int j = tid; j < K1; j += 512)
        ts[2048 + j] = times[(size_t)(B_SZ * L_SZ) + (size_t)b * L_SZ + j];
    __syncthreads();
    int warp = tid >> 5, lane = tid & 31;
    int g = blockIdx.x * 16 + warp;
    float ec0 = g_ec[g], ec1 = g_ec[G_SZ + g];
    float mg = (float)g + 0.5f;
    uint32_t base = ((uint32_t)(b * G_SZ + g)) << 12;

    // pass A: min distance among valid nonzero events (registers only)
    float umin0 = 1e9f, umin1 = 1e9f;
    for (int n0 = lane * 4; n0 < K0; n0 += 128) {
        float4 t4 = *(const float4*)&ts[n0];
        #pragma unroll
        for (int q = 0; q < 4; q++) {
            float tm = (q == 0) ? t4.x : (q == 1) ? t4.y : (q == 2) ? t4.z : t4.w;
            bool valid = (n0 + q < rl0) && (tm != 0.f);
            umin0 = fminf(umin0, valid ? fabsf(tm - mg) : 1e9f);
        }
    }
    for (int n0 = lane * 4; n0 < K1; n0 += 128) {
        float4 t4 = *(const float4*)&ts[2048 + n0];
        #pragma unroll
        for (int q = 0; q < 4; q++) {
            float tm = (q == 0) ? t4.x : (q == 1) ? t4.y : (q == 2) ? t4.z : t4.w;
            bool valid = (n0 + q < rl1) && (tm != 0.f);
            umin1 = fminf(umin1, valid ? fabsf(tm - mg) : 1e9f);
        }
    }
    #pragma unroll
    for (int off = 16; off; off >>= 1) {
        umin0 = fminf(umin0, __shfl_xor_sync(0xffffffffu, umin0, off));
        umin1 = fminf(umin1, __shfl_xor_sync(0xffffffffu, umin1, off));
    }
    float b0 = w_raw4(tab, mg + fminf(umin0, 1023.5f), mg, ec0);
    float b1 = w_raw4(tab, mg + fminf(umin1, 1023.5f), mg, ec1);
    float bound = fmaxf(fmaxf(b0, b1), 1.0f);
    float invb = 1.0f / bound;

    // pass B: interp + quantize + fp32 sum of quantized values
    float sum = 0.f;
    #pragma unroll 1
    for (int seg = 0; seg < 2; seg++) {
        int K  = seg ? K1 : K0;
        int rl = seg ? rl1 : rl0;
        float ec = seg ? ec1 : ec0;
        int off_ts = seg ? 2048 : 0;
        for (int n0 = lane * 4; n0 < K; n0 += 128) {
            float4 t4 = *(const float4*)&ts[off_ts + n0];
            float w[4];
            #pragma unroll
            for (int q = 0; q < 4; q++) {
                float tm = (q == 0) ? t4.x : (q == 1) ? t4.y : (q == 2) ? t4.z : t4.w;
                float wr = w_raw4(tab, tm, mg, ec);
                w[q] = (n0 + q < rl) ? wr * invb : 0.f;
            }
            __half2 p0 = __floats2half2_rn(w[0], w[1]);
            __half2 p1 = __floats2half2_rn(w[2], w[3]);
            float2 f0 = __half22float2(p0);
            float2 f1 = __half22float2(p1);
            sum += (f0.x + f0.y) + (f1.x + f1.y);
            uint2 pk = make_uint2(*(uint32_t*)&p0, *(uint32_t*)&p1);
            *(uint2*)&g_w[base + off_ts + n0] = pk;
        }
    }
    #pragma unroll
    for (int off = 16; off; off >>= 1) sum += __shfl_xor_sync(0xffffffffu, sum, off);
    if (lane == 0) g_sc[b * G_SZ + g] = 1.0f / sum;
}

// ---------------- fp16 mma.sync GEMM: ragged K, 128x128 tiles, swizzled ----------------
#define KT 64
#define STAGES 3
#define A_TILE_B (128 * 128)           // 16384 (128 rows x 128B)
#define STG_B (2 * A_TILE_B)           // 32768

__global__ void __launch_bounds__(256, 2) k_gemm(const int* __restrict__ real_len,
                                                 float* __restrict__ out) {
    extern __shared__ char smG[];
    uint32_t smb = smem_u32(smG);
    float* smInv = (float*)(smG + STAGES * STG_B);
    int tid = threadIdx.x, wid = tid >> 5, lane = tid & 31;
    int b  = blockIdx.x;                      // b fastest -> waves mix all b's
    int g0 = (blockIdx.y & 7) * 128;
    int d0 = (blockIdx.y >> 3) * 128;
    int wm = wid >> 2, wn = wid & 3;          // 2 x 4 warps; warp tile 64g x 32d

    int nk0 = (((real_len[b] + 63) & ~63) >> 6);
    int nk1 = (((real_len[B_SZ + b] + 63) & ~63) >> 6);
    int nk  = nk0 + nk1;                      // 2..64

    if (tid < 128) smInv[tid] = g_sc[b * G_SZ + g0 + tid];

    const __half* wbase = g_w + (((uint32_t)(b * G_SZ + g0)) << 12);
    const __half* ebase = g_e + (((uint32_t)(b * D_EMBD + d0)) << 12);

    auto kof = [&](int i) { return i < nk0 ? i * KT : (i - nk0) * KT + 2048; };

    auto load_stage = [&](int s, int k0) {
        uint32_t st = smb + s * STG_B;
        #pragma unroll
        for (int t = 0; t < 4; t++) {           // A: 128 rows x 8 chunks
            int id = tid + t * 256;
            int row = id >> 3, c = id & 7;
            uint32_t col = (uint32_t)(c * 16) ^ (uint32_t)((row & 7) << 4);
            cp16(st + row * 128 + col, wbase + ((uint32_t)row << 12) + k0 + c * 8);
        }
        #pragma unroll
        for (int t = 0; t < 4; t++) {           // B: 128 rows x 8 chunks
            int id = tid + t * 256;
            int row = id >> 3, c = id & 7;
            uint32_t col = (uint32_t)(c * 16) ^ (uint32_t)((row & 7) << 4);
            cp16(st + A_TILE_B + row * 128 + col, ebase + ((uint32_t)row << 12) + k0 + c * 8);
        }
        asm volatile("cp.async.commit_group;" ::: "memory");
    };

    float acc[4][4][4];
    #pragma unroll
    for (int i = 0; i < 4; i++)
        #pragma unroll
        for (int j = 0; j < 4; j++)
            #pragma unroll
            for (int q = 0; q < 4; q++) acc[i][j][q] = 0.f;

    load_stage(0, kof(0));
    load_stage(1, kof(1));

    int a_row = (lane & 7) + ((lane >> 3) & 1) * 8;
    int a_col = (lane >> 4) * 16;
    int b_grp = lane >> 3;
    int b_row = (b_grp >> 1) * 8 + (lane & 7);
    int b_col = (b_grp & 1) * 16;
    uint32_t lxor = (uint32_t)((lane & 7) << 4);

    for (int i = 0; i < nk; i++) {
        if (i < nk - 1) asm volatile("cp.async.wait_group 1;" ::: "memory");
        else            asm volatile("cp.async.wait_group 0;" ::: "memory");
        __syncthreads();

        int s = i % 3;
        uint32_t abase = smb + s * STG_B;
        uint32_t bbase = abase + A_TILE_B;
        #pragma unroll
        for (int ks = 0; ks < 4; ks++) {
            uint32_t acol = ((uint32_t)(ks * 32 + a_col)) ^ lxor;
            uint32_t bcol = ((uint32_t)(ks * 32 + b_col)) ^ lxor;
            uint32_t af[4][4], bf[2][4];
            #pragma unroll
            for (int m = 0; m < 4; m++)
                ldm_x4(af[m], abase + (wm * 64 + m * 16 + a_row) * 128 + acol);
            #pragma unroll
            for (int jp = 0; jp < 2; jp++)
                ldm_x4(bf[jp], bbase + (wn * 32 + jp * 16 + b_row) * 128 + bcol);
            #pragma unroll
            for (int m = 0; m < 4; m++)
                #pragma unroll
                for (int j = 0; j < 4; j++)
                    mma16816(acc[m][j], af[m], bf[j >> 1][(j & 1) * 2], bf[j >> 1][(j & 1) * 2 + 1]);
        }
        if (i + 2 < nk) load_stage((i + 2) % 3, kof(i + 2));
    }

    #pragma unroll
    for (int m = 0; m < 4; m++) {
        int r0 = wm * 64 + m * 16 + (lane >> 2);
        float sc0 = smInv[r0], sc1 = smInv[r0 + 8];
        uint32_t gr0 = (uint32_t)(b * G_SZ + g0 + r0) * D_EMBD + d0 + wn * 32;
        #pragma unroll
        for (int j = 0; j < 4; j++) {
            int col = j * 8 + (lane & 3) * 2;
            *(float2*)(out + gr0 + col) =
                make_float2(acc[m][j][0] * sc0, acc[m][j][1] * sc0);
            *(float2*)(out + gr0 + 8 * D_EMBD + col) =
                make_float2(acc[m][j][2] * sc1, acc[m][j][3] * sc1);
        }
    }
}

// ---------------- launch ----------------
extern "C" void kernel_launch(void* const* d_in, const int* in_sizes, int n_in,
                              void* d_out, int out_size) {
    const float* times    = (const float*)d_in[0];
    const float* type_emb = (const float*)d_in[1];
    const int*   real_len = (const int*)d_in[2];
    float* out = (float*)d_out;
    (void)in_sizes; (void)n_in; (void)out_size;

    size_t smem_w = (size_t)(4 * TAB_N + N_EV) * sizeof(float);              // 80 KB
    size_t smem_g = STAGES * STG_B + 128 * sizeof(float);                    // ~96.5 KB
    cudaFuncSetAttribute(k_weights, cudaFuncAttributeMaxDynamicSharedMemorySize, (int)smem_w);
    cudaFuncSetAttribute(k_gemm,    cudaFuncAttributeMaxDynamicSharedMemorySize, (int)smem_g);

    k_table<<<(TAB_N + 1 + 7) / 8, 256>>>();             // warp per entry, packs g_tab4
    k_ec<<<T_TYPES * G_SZ / 8, 256>>>(type_emb);         // warp per (t,g)
    k_emb_t<<<dim3(N_EV / 32, B_SZ), 256>>>(times, type_emb, real_len);
    k_weights<<<dim3(G_SZ / 16, B_SZ), 512, smem_w>>>(times, real_len);
    k_gemm<<<dim3(B_SZ, (G_SZ / 128) * (D_EMBD / 128)), 256, smem_g>>>(real_len, out);
}